// round 15
// baseline (speedup 1.0000x reference)
#include <cuda_runtime.h>
#include <cuda_bf16.h>
#include <math.h>
#include <stdint.h>

#define Mdim 256
#define Ldim 4096
#define Tdim 2048
#define LOG2E_F 1.4426950408889634f

// ---------------- device scratch ----------------
__device__ float g_Rre[Mdim*Mdim], g_Rim[Mdim*Mdim];
__device__ float g_Gre[Mdim*Mdim], g_Gim[Mdim*Mdim];
__device__ float g_Xa_re[Mdim*Mdim], g_Xa_im[Mdim*Mdim];
__device__ float g_Xb_re[Mdim*Mdim], g_Xb_im[Mdim*Mdim];
__device__ float g_P_re[Mdim*Mdim],  g_P_im[Mdim*Mdim];
__device__ float g_part_re[48*Mdim*Mdim], g_part_im[48*Mdim*Mdim];
__device__ float g_Atre[Ldim*Mdim], g_Atim[Ldim*Mdim];
__device__ float g_Ztre[Ldim*Mdim], g_Ztim[Ldim*Mdim];
__device__ float g_GZre[Ldim*Mdim], g_GZim[Ldim*Mdim];
__device__ float g_v[Ldim], g_u[Ldim], g_up[Ldim], g_attn[Ldim], g_gate[Ldim];
__device__ float g_scal[4];   // [0]=alpha  [1]=kv2min [2]=kv2max

__device__ __forceinline__ float warp_sum(float v) {
    #pragma unroll
    for (int o = 16; o > 0; o >>= 1) v += __shfl_xor_sync(0xffffffffu, v, o);
    return v;
}

// ---------------- smem helpers ----------------
__device__ __forceinline__ uint32_t smem_u32(const void* p) {
    uint32_t a;
    asm("{ .reg .u64 t; cvta.to.shared.u64 t, %1; cvt.u32.u64 %0, t; }" : "=r"(a) : "l"(p));
    return a;
}
__device__ __forceinline__ uint32_t lds32(uint32_t a) {
    uint32_t v;
    asm volatile("ld.shared.b32 %0, [%1];" : "=r"(v) : "r"(a));
    return v;
}
__device__ __forceinline__ void sts128(uint32_t a, uint32_t x, uint32_t y,
                                       uint32_t z, uint32_t w) {
    asm volatile("st.shared.v4.b32 [%0], {%1,%2,%3,%4};"
                 :: "r"(a), "r"(x), "r"(y), "r"(z), "r"(w) : "memory");
}
__device__ __forceinline__ uint32_t cvt_tf32(float x) {
    uint32_t r;
    asm("cvt.rna.tf32.f32 %0, %1;" : "=r"(r) : "f"(x));
    return r;
}
#define MMAT32(d, a, b) \
    asm volatile("mma.sync.aligned.m16n8k8.row.col.f32.tf32.tf32.f32 " \
        "{%0,%1,%2,%3},{%4,%5,%6,%7},{%8,%9},{%0,%1,%2,%3};" \
        : "+f"((d)[0]), "+f"((d)[1]), "+f"((d)[2]), "+f"((d)[3]) \
        : "r"((a)[0]), "r"((a)[1]), "r"((a)[2]), "r"((a)[3]), "r"((b)[0]), "r"((b)[1]))

#define PITCHB 144
#define PLSZ   18432
#define ENG_SMEM2 (8*PLSZ)

// convert one 128x32 fp32 tile -> 2 tf32 split planes in smem (sign/weight folded)
__device__ __forceinline__ void conv_tile2(uint32_t sa, int tbase,
                                           const float* __restrict__ src, int row0, int ld,
                                           int k0, const float* __restrict__ w, float sgn)
{
    int tid = threadIdx.x;
    uint32_t p0 = sa + tbase*PLSZ;
    uint32_t p1 = p0 + PLSZ;
    #pragma unroll
    for (int p = 0; p < 4; p++) {
        int idx = tid + p*256;
        int row = idx >> 3, c4 = idx & 7;
        float4 v = *(const float4*)(src + (size_t)(row0+row)*ld + k0 + c4*4);
        if (w) {
            float4 wv = *(const float4*)(w + k0 + c4*4);
            v.x *= wv.x; v.y *= wv.y; v.z *= wv.z; v.w *= wv.w;
        }
        v.x *= sgn; v.y *= sgn; v.z *= sgn; v.w *= sgn;
        uint32_t h0 = cvt_tf32(v.x), h1 = cvt_tf32(v.y);
        uint32_t h2 = cvt_tf32(v.z), h3 = cvt_tf32(v.w);
        uint32_t m0 = cvt_tf32(v.x - __uint_as_float(h0));
        uint32_t m1 = cvt_tf32(v.y - __uint_as_float(h1));
        uint32_t m2 = cvt_tf32(v.z - __uint_as_float(h2));
        uint32_t m3 = cvt_tf32(v.w - __uint_as_float(h3));
        uint32_t off = row*PITCHB + c4*16;
        sts128(p0 + off, h0, h1, h2, h3);
        sts128(p1 + off, m0, m1, m2, m3);
    }
}

// ============================================================================
// split-tf32 complex GEMM via mma.sync m16n8k8 (q-chain ONLY — G and GZt)
// ============================================================================
__global__ __launch_bounds__(256, 1)
void cgemm_mma(const float* __restrict__ Pre, const float* __restrict__ Pim, int ldp,
               const float* __restrict__ Qre, const float* __restrict__ Qim, int ldq,
               float* __restrict__ Cre, float* __restrict__ Cim, int ldc,
               int Kper, int conj, const float* __restrict__ w, int partElems, int yoff)
{
    extern __shared__ char dsm[];
    uint32_t sa = smem_u32(dsm);
    int tid = threadIdx.x;
    int wid = tid >> 5, lane = tid & 31;
    int g = lane >> 2, t4 = lane & 3;
    int warpM = wid >> 2, warpN = wid & 3;
    int i0 = (blockIdx.y + yoff) * 128, j0 = blockIdx.x * 128;
    int plane = blockIdx.z & 1, ks = blockIdx.z >> 1;

    const float* A0 = (conj && plane) ? Pim : Pre;
    const float* A1 = (conj && plane) ? Pre : Pim;
    float s1 = ((conj && plane) || (!conj && !plane)) ? -1.f : 1.f;
    const float* B0 = (!conj && plane) ? Qim : Qre;
    const float* B1 = (!conj && plane) ? Qre : Qim;

    float acc[4][4][4] = {};

    int nCh = Kper >> 5;
    for (int ch = 0; ch < nCh; ch++) {
        int k0 = ks * Kper + ch * 32;
        conv_tile2(sa, 0, A0, i0, ldp, k0, w, 1.f);
        conv_tile2(sa, 2, A1, i0, ldp, k0, w, s1);
        conv_tile2(sa, 4, B0, j0, ldq, k0, (const float*)0, 1.f);
        conv_tile2(sa, 6, B1, j0, ldq, k0, (const float*)0, 1.f);
        __syncthreads();

        const int ta[6] = {0, 0, 1, 2, 2, 3};
        const int tb[6] = {4, 5, 4, 6, 7, 6};
        #pragma unroll
        for (int ps = 0; ps < 6; ps++) {
            uint32_t ab = sa + ta[ps]*PLSZ;
            uint32_t bb = sa + tb[ps]*PLSZ;
            #pragma unroll
            for (int kk = 0; kk < 4; kk++) {
                uint32_t afr[4][4], bfr[4][2];
                #pragma unroll
                for (int am = 0; am < 4; am++) {
                    uint32_t r0 = ab + (warpM*64 + am*16 + g)*PITCHB + (kk*8 + t4)*4;
                    afr[am][0] = lds32(r0);
                    afr[am][1] = lds32(r0 + 8*PITCHB);
                    afr[am][2] = lds32(r0 + 16);
                    afr[am][3] = lds32(r0 + 8*PITCHB + 16);
                }
                #pragma unroll
                for (int bn = 0; bn < 4; bn++) {
                    uint32_t r0 = bb + (warpN*32 + bn*8 + g)*PITCHB + (kk*8 + t4)*4;
                    bfr[bn][0] = lds32(r0);
                    bfr[bn][1] = lds32(r0 + 16);
                }
                #pragma unroll
                for (int am = 0; am < 4; am++)
                    #pragma unroll
                    for (int bn = 0; bn < 4; bn++)
                        MMAT32(acc[am][bn], afr[am], bfr[bn]);
            }
        }
        __syncthreads();
    }

    float* dst = plane ? Cim : Cre;
    size_t zoff = (size_t)ks * partElems;
    #pragma unroll
    for (int am = 0; am < 4; am++) {
        #pragma unroll
        for (int bn = 0; bn < 4; bn++) {
            int r = i0 + warpM*64 + am*16 + g;
            int c = j0 + warpN*32 + bn*8 + 2*t4;
            float2 v0 = make_float2(acc[am][bn][0], acc[am][bn][1]);
            float2 v1 = make_float2(acc[am][bn][2], acc[am][bn][3]);
            *(float2*)(dst + zoff + (size_t)r*ldc + c) = v0;
            *(float2*)(dst + zoff + (size_t)(r+8)*ldc + c) = v1;
        }
    }
}

// ============================================================================
// High-ILP fp32 SIMT complex GEMMs: BM=128, BN=64, BK=16, TM=8, TN=4.
// ============================================================================
#define BBM 128
#define BBN 64
#define BBK 16

// Hermitian csyrk: 6 lower/diagonal tiles of C = (A*diag(w)) A^H.
__global__ __launch_bounds__(256)
void csyrk_big(float* __restrict__ Pre, float* __restrict__ Pim,
               const float* __restrict__ Are, const float* __restrict__ Aim,
               const float* __restrict__ w, int lda, int kChunk)
{
    __shared__ float as_re[BBK][BBM+4], as_im[BBK][BBM+4];
    __shared__ float bs_re[BBK][BBN+4], bs_im[BBK][BBN+4];
    const int tbi[6] = {0, 0, 128, 128, 128, 128};
    const int tbj[6] = {0, 64, 0, 64, 128, 192};
    int i0 = tbi[blockIdx.x], j0 = tbj[blockIdx.x];
    int k0 = blockIdx.z * kChunk;
    int t  = threadIdx.x;
    int tx = t & 15, ty = t >> 4;
    int arow = t >> 2, ak4 = (t & 3) * 4;
    float cre[8][4] = {}, cim[8][4] = {};

    for (int kb = 0; kb < kChunk; kb += BBK) {
        int kbase = k0 + kb;
        float4 wv;
        if (w) wv = *(const float4*)(w + kbase + ak4);
        else   wv = make_float4(1.f, 1.f, 1.f, 1.f);
        #pragma unroll
        for (int r = 0; r < 2; r++) {
            int row = arow + r*64;
            float4 vr = *(const float4*)(Are + (size_t)(i0+row)*lda + kbase + ak4);
            float4 vi = *(const float4*)(Aim + (size_t)(i0+row)*lda + kbase + ak4);
            as_re[ak4+0][row] = vr.x*wv.x; as_re[ak4+1][row] = vr.y*wv.y;
            as_re[ak4+2][row] = vr.z*wv.z; as_re[ak4+3][row] = vr.w*wv.w;
            as_im[ak4+0][row] = vi.x*wv.x; as_im[ak4+1][row] = vi.y*wv.y;
            as_im[ak4+2][row] = vi.z*wv.z; as_im[ak4+3][row] = vi.w*wv.w;
        }
        {
            int col = t >> 2;
            float4 vr = *(const float4*)(Are + (size_t)(j0+col)*lda + kbase + ak4);
            float4 vi = *(const float4*)(Aim + (size_t)(j0+col)*lda + kbase + ak4);
            bs_re[ak4+0][col] = vr.x; bs_re[ak4+1][col] = vr.y;
            bs_re[ak4+2][col] = vr.z; bs_re[ak4+3][col] = vr.w;
            bs_im[ak4+0][col] = vi.x; bs_im[ak4+1][col] = vi.y;
            bs_im[ak4+2][col] = vi.z; bs_im[ak4+3][col] = vi.w;
        }
        __syncthreads();
        #pragma unroll
        for (int kk = 0; kk < BBK; kk++) {
            float ar[8], ai[8], br[4], bi[4];
            #pragma unroll
            for (int i = 0; i < 8; i++) { ar[i] = as_re[kk][ty*8+i]; ai[i] = as_im[kk][ty*8+i]; }
            #pragma unroll
            for (int j = 0; j < 4; j++) { br[j] = bs_re[kk][tx*4+j]; bi[j] = bs_im[kk][tx*4+j]; }
            #pragma unroll
            for (int i = 0; i < 8; i++)
                #pragma unroll
                for (int j = 0; j < 4; j++) {
                    cre[i][j] += ar[i]*br[j];
                    cre[i][j] += ai[i]*bi[j];
                    cim[i][j] += ai[i]*br[j];
                    cim[i][j] -= ar[i]*bi[j];
                }
        }
        __syncthreads();
    }
    size_t off = (size_t)blockIdx.z * (Mdim*Mdim);
    #pragma unroll
    for (int i = 0; i < 8; i++) {
        int gi = i0 + ty*8 + i, gj = j0 + tx*4;
        *(float4*)(Pre + off + (size_t)gi*Mdim + gj) = make_float4(cre[i][0], cre[i][1], cre[i][2], cre[i][3]);
        *(float4*)(Pim + off + (size_t)gi*Mdim + gj) = make_float4(cim[i][0], cim[i][1], cim[i][2], cim[i][3]);
    }
}

// nn variant: C[i,j] = sum_k A[i,k]*B[k,j]
__global__ __launch_bounds__(256)
void cgemm_big(float* __restrict__ Cre, float* __restrict__ Cim,
               const float* __restrict__ Are, const float* __restrict__ Aim, int lda,
               const float* __restrict__ Bre, const float* __restrict__ Bim, int ldb,
               int kChunk, int MNpart, int yoff)
{
    __shared__ float as_re[BBK][BBM+4], as_im[BBK][BBM+4];
    __shared__ float bs_re[BBK][BBN+4], bs_im[BBK][BBN+4];
    int i0 = (blockIdx.y + yoff) * BBM, j0 = blockIdx.x * BBN;
    int k0 = blockIdx.z * kChunk;
    int t  = threadIdx.x;
    int tx = t & 15, ty = t >> 4;
    int arow = t >> 2, ak4 = (t & 3) * 4;
    int bk = t >> 4, bc4 = (t & 15) * 4;
    float cre[8][4] = {}, cim[8][4] = {};

    for (int kb = 0; kb < kChunk; kb += BBK) {
        int kbase = k0 + kb;
        #pragma unroll
        for (int r = 0; r < 2; r++) {
            int row = arow + r*64;
            float4 vr = *(const float4*)(Are + (size_t)(i0+row)*lda + kbase + ak4);
            float4 vi = *(const float4*)(Aim + (size_t)(i0+row)*lda + kbase + ak4);
            as_re[ak4+0][row] = vr.x; as_re[ak4+1][row] = vr.y;
            as_re[ak4+2][row] = vr.z; as_re[ak4+3][row] = vr.w;
            as_im[ak4+0][row] = vi.x; as_im[ak4+1][row] = vi.y;
            as_im[ak4+2][row] = vi.z; as_im[ak4+3][row] = vi.w;
        }
        {
            float4 vr = *(const float4*)(Bre + (size_t)(kbase+bk)*ldb + j0 + bc4);
            float4 vi = *(const float4*)(Bim + (size_t)(kbase+bk)*ldb + j0 + bc4);
            *(float4*)&bs_re[bk][bc4] = vr;
            *(float4*)&bs_im[bk][bc4] = vi;
        }
        __syncthreads();
        #pragma unroll
        for (int kk = 0; kk < BBK; kk++) {
            float ar[8], ai[8], br[4], bi[4];
            #pragma unroll
            for (int i = 0; i < 8; i++) { ar[i] = as_re[kk][ty*8+i]; ai[i] = as_im[kk][ty*8+i]; }
            #pragma unroll
            for (int j = 0; j < 4; j++) { br[j] = bs_re[kk][tx*4+j]; bi[j] = bs_im[kk][tx*4+j]; }
            #pragma unroll
            for (int i = 0; i < 8; i++)
                #pragma unroll
                for (int j = 0; j < 4; j++) {
                    cre[i][j] += ar[i]*br[j];
                    cre[i][j] -= ai[i]*bi[j];
                    cim[i][j] += ar[i]*bi[j];
                    cim[i][j] += ai[i]*br[j];
                }
        }
        __syncthreads();
    }
    size_t off = (size_t)blockIdx.z * MNpart;
    #pragma unroll
    for (int i = 0; i < 8; i++) {
        int gi = i0 + ty*8 + i, gj = j0 + tx*4;
        *(float4*)(Cre + off + (size_t)gi*ldb + gj) = make_float4(cre[i][0], cre[i][1], cre[i][2], cre[i][3]);
        *(float4*)(Cim + off + (size_t)gi*ldb + gj) = make_float4(cim[i][0], cim[i][1], cim[i][2], cim[i][3]);
    }
}

// Newton GEMM1 with fused B = 2*Xbase - sum(parts 16..31) (bit-identical to
// reduce_newton's expression) + Xn materialization by blockIdx.y==0 CTAs.
// A = R. kChunk = 16 (one BBK pass), grid (4,2,16).
__global__ __launch_bounds__(256)
void cgemm_bfn(float* __restrict__ Cre, float* __restrict__ Cim,
               const float* __restrict__ Are, const float* __restrict__ Aim, int lda,
               const float* __restrict__ Xbre, const float* __restrict__ Xbim, int ldb,
               float* __restrict__ XnRe, float* __restrict__ XnIm)
{
    __shared__ float as_re[BBK][BBM+4], as_im[BBK][BBM+4];
    __shared__ float bs_re[BBK][BBN+4], bs_im[BBK][BBN+4];
    int i0 = blockIdx.y * BBM, j0 = blockIdx.x * BBN;
    int kbase = blockIdx.z * BBK;
    int t  = threadIdx.x;
    int tx = t & 15, ty = t >> 4;
    int arow = t >> 2, ak4 = (t & 3) * 4;
    int bk = t >> 4, bc4 = (t & 15) * 4;
    float cre[8][4] = {}, cim[8][4] = {};

    #pragma unroll
    for (int r = 0; r < 2; r++) {
        int row = arow + r*64;
        float4 vr = *(const float4*)(Are + (size_t)(i0+row)*lda + kbase + ak4);
        float4 vi = *(const float4*)(Aim + (size_t)(i0+row)*lda + kbase + ak4);
        as_re[ak4+0][row] = vr.x; as_re[ak4+1][row] = vr.y;
        as_re[ak4+2][row] = vr.z; as_re[ak4+3][row] = vr.w;
        as_im[ak4+0][row] = vi.x; as_im[ak4+1][row] = vi.y;
        as_im[ak4+2][row] = vi.z; as_im[ak4+3][row] = vi.w;
    }
    {
        size_t eoff = (size_t)(kbase+bk)*ldb + j0 + bc4;
        float4 xr = *(const float4*)(Xbre + eoff);
        float4 xi = *(const float4*)(Xbim + eoff);
        float4 sr = make_float4(0.f,0.f,0.f,0.f), si = make_float4(0.f,0.f,0.f,0.f);
        for (int z = 16; z < 32; z++) {
            float4 pr = *(const float4*)(g_part_re + (size_t)z*65536 + eoff);
            float4 pi = *(const float4*)(g_part_im + (size_t)z*65536 + eoff);
            sr.x += pr.x; sr.y += pr.y; sr.z += pr.z; sr.w += pr.w;
            si.x += pi.x; si.y += pi.y; si.z += pi.z; si.w += pi.w;
        }
        float4 vr = make_float4(2.f*xr.x - sr.x, 2.f*xr.y - sr.y, 2.f*xr.z - sr.z, 2.f*xr.w - sr.w);
        float4 vi = make_float4(2.f*xi.x - si.x, 2.f*xi.y - si.y, 2.f*xi.z - si.z, 2.f*xi.w - si.w);
        *(float4*)&bs_re[bk][bc4] = vr;
        *(float4*)&bs_im[bk][bc4] = vi;
        if (blockIdx.y == 0 && blockIdx.x == 0) {
            // x==0 covers cols 0..63 only; need all x to write. Use x-dependent cols.
        }
        if (blockIdx.y == 0) {
            *(float4*)(XnRe + eoff) = vr;
            *(float4*)(XnIm + eoff) = vi;
        }
    }
    __syncthreads();
    #pragma unroll
    for (int kk = 0; kk < BBK; kk++) {
        float ar[8], ai[8], br[4], bi[4];
        #pragma unroll
        for (int i = 0; i < 8; i++) { ar[i] = as_re[kk][ty*8+i]; ai[i] = as_im[kk][ty*8+i]; }
        #pragma unroll
        for (int j = 0; j < 4; j++) { br[j] = bs_re[kk][tx*4+j]; bi[j] = bs_im[kk][tx*4+j]; }
        #pragma unroll
        for (int i = 0; i < 8; i++)
            #pragma unroll
            for (int j = 0; j < 4; j++) {
                cre[i][j] += ar[i]*br[j];
                cre[i][j] -= ai[i]*bi[j];
                cim[i][j] += ar[i]*bi[j];
                cim[i][j] += ai[i]*br[j];
            }
    }
    __syncthreads();
    size_t off = (size_t)blockIdx.z * 65536;
    #pragma unroll
    for (int i = 0; i < 8; i++) {
        int gi = i0 + ty*8 + i, gj = j0 + tx*4;
        *(float4*)(Cre + off + (size_t)gi*ldb + gj) = make_float4(cre[i][0], cre[i][1], cre[i][2], cre[i][3]);
        *(float4*)(Cim + off + (size_t)gi*ldb + gj) = make_float4(cim[i][0], cim[i][1], cim[i][2], cim[i][3]);
    }
}

// nn variant with fused B-reduction (sum parts 0..SK-1, ascending)
__global__ __launch_bounds__(256)
void cgemm_fsum(float* __restrict__ Cre, float* __restrict__ Cim,
                const float* __restrict__ Are, const float* __restrict__ Aim, int lda,
                const float* __restrict__ Bpre, const float* __restrict__ Bpim, int ldb,
                int SK, int kChunk, int MNpart)
{
    __shared__ float as_re[BBK][BBM+4], as_im[BBK][BBM+4];
    __shared__ float bs_re[BBK][BBN+4], bs_im[BBK][BBN+4];
    int i0 = blockIdx.y * BBM, j0 = blockIdx.x * BBN;
    int k0 = blockIdx.z * kChunk;
    int t  = threadIdx.x;
    int tx = t & 15, ty = t >> 4;
    int arow = t >> 2, ak4 = (t & 3) * 4;
    int bk = t >> 4, bc4 = (t & 15) * 4;
    float cre[8][4] = {}, cim[8][4] = {};

    for (int kb = 0; kb < kChunk; kb += BBK) {
        int kbase = k0 + kb;
        #pragma unroll
        for (int r = 0; r < 2; r++) {
            int row = arow + r*64;
            float4 vr = *(const float4*)(Are + (size_t)(i0+row)*lda + kbase + ak4);
            float4 vi = *(const float4*)(Aim + (size_t)(i0+row)*lda + kbase + ak4);
            as_re[ak4+0][row] = vr.x; as_re[ak4+1][row] = vr.y;
            as_re[ak4+2][row] = vr.z; as_re[ak4+3][row] = vr.w;
            as_im[ak4+0][row] = vi.x; as_im[ak4+1][row] = vi.y;
            as_im[ak4+2][row] = vi.z; as_im[ak4+3][row] = vi.w;
        }
        {
            size_t eoff = (size_t)(kbase+bk)*ldb + j0 + bc4;
            float4 vr = make_float4(0.f,0.f,0.f,0.f), vi = make_float4(0.f,0.f,0.f,0.f);
            for (int z = 0; z < SK; z++) {
                float4 pr = *(const float4*)(Bpre + (size_t)z*65536 + eoff);
                float4 pi = *(const float4*)(Bpim + (size_t)z*65536 + eoff);
                vr.x += pr.x; vr.y += pr.y; vr.z += pr.z; vr.w += pr.w;
                vi.x += pi.x; vi.y += pi.y; vi.z += pi.z; vi.w += pi.w;
            }
            *(float4*)&bs_re[bk][bc4] = vr;
            *(float4*)&bs_im[bk][bc4] = vi;
        }
        __syncthreads();
        #pragma unroll
        for (int kk = 0; kk < BBK; kk++) {
            float ar[8], ai[8], br[4], bi[4];
            #pragma unroll
            for (int i = 0; i < 8; i++) { ar[i] = as_re[kk][ty*8+i]; ai[i] = as_im[kk][ty*8+i]; }
            #pragma unroll
            for (int j = 0; j < 4; j++) { br[j] = bs_re[kk][tx*4+j]; bi[j] = bs_im[kk][tx*4+j]; }
            #pragma unroll
            for (int i = 0; i < 8; i++)
                #pragma unroll
                for (int j = 0; j < 4; j++) {
                    cre[i][j] += ar[i]*br[j];
                    cre[i][j] -= ai[i]*bi[j];
                    cim[i][j] += ar[i]*bi[j];
                    cim[i][j] += ai[i]*br[j];
                }
        }
        __syncthreads();
    }
    size_t off = (size_t)blockIdx.z * MNpart;
    #pragma unroll
    for (int i = 0; i < 8; i++) {
        int gi = i0 + ty*8 + i, gj = j0 + tx*4;
        *(float4*)(Cre + off + (size_t)gi*ldb + gj) = make_float4(cre[i][0], cre[i][1], cre[i][2], cre[i][3]);
        *(float4*)(Cim + off + (size_t)gi*ldb + gj) = make_float4(cim[i][0], cim[i][1], cim[i][2], cim[i][3]);
    }
}

// ---------------- reduces ----------------
__global__ void reduce_RG(float* __restrict__ Cre, float* __restrict__ Cim,
                          int SK, int ridge, int zoff) {
    int e = blockIdx.x * 256 + threadIdx.x;
    float sr = 0.f, si = 0.f;
    for (int z = zoff; z < zoff + SK; z++) { sr += g_part_re[z*65536 + e]; si += g_part_im[z*65536 + e]; }
    if (ridge && (e >> 8) == (e & 255)) sr += 0.01f;
    Cre[e] = sr; Cim[e] = si;
}
__global__ void mirror_R() {
    int e = blockIdx.x * 256 + threadIdx.x;
    int i = e >> 7, j = 128 + (e & 127);
    g_Rre[i*256 + j] =  g_Rre[j*256 + i];
    g_Rim[i*256 + j] = -g_Rim[j*256 + i];
}
__global__ void reduce_newton(float* __restrict__ Xnre, float* __restrict__ Xnim,
                              const float* __restrict__ Xre, const float* __restrict__ Xim,
                              int SK, int zoff)
{
    int e = blockIdx.x * 256 + threadIdx.x;
    float sr = 0.f, si = 0.f;
    for (int z = zoff; z < zoff + SK; z++) { sr += g_part_re[z*65536 + e]; si += g_part_im[z*65536 + e]; }
    Xnre[e] = 2.f*Xre[e] - sr;
    Xnim[e] = 2.f*Xim[e] - si;
}

// ---------------- alpha ; X1 = 2aI - a^2 R ----------------
__global__ void trace_alpha() {
    __shared__ float red[1024];
    __shared__ float s_fro;
    int t = threadIdx.x;
    float fro = 0.f;
    for (int e = t; e < 65536; e += 1024) {
        float a = g_Rre[e], b = g_Rim[e];
        fro += a*a + b*b;
    }
    red[t] = fro; __syncthreads();
    for (int o = 512; o > 0; o >>= 1) { if (t < o) red[t] += red[t+o]; __syncthreads(); }
    if (t == 0) s_fro = red[0];
    __syncthreads();
    float tr = 0.f;
    for (int i = t; i < 256; i += 1024) tr += g_Rre[i*257];
    red[t] = tr; __syncthreads();
    for (int o = 512; o > 0; o >>= 1) { if (t < o) red[t] += red[t+o]; __syncthreads(); }
    if (t == 0) g_scal[0] = red[0] / s_fro;
}
__global__ void init_X1(float* __restrict__ Xre, float* __restrict__ Xim) {
    int e = blockIdx.x * 256 + threadIdx.x;
    int i = e >> 8, j = e & 255;
    float a = g_scal[0];
    float a2 = a * a;
    Xre[e] = -a2 * g_Rre[e] + ((i == j) ? 2.f*a : 0.f);
    Xim[e] = -a2 * g_Rim[e];
}

// ---------------- Bc = conj(symmetrize(Rinv)) ----------------
__global__ void symm_conj(const float* __restrict__ Xre, const float* __restrict__ Xim,
                          float* __restrict__ Bre, float* __restrict__ Bim) {
    int e = blockIdx.x * 256 + threadIdx.x;
    int i = e >> 8, j = e & 255;
    Bre[e] = 0.5f * (Xre[i*256 + j] + Xre[j*256 + i]);
    Bim[e] = 0.5f * (Xim[j*256 + i] - Xim[i*256 + j]);
}

// ---------------- transpose A -> At [L][M] ----------------
__global__ void transposeA(const float* __restrict__ Are, const float* __restrict__ Aim) {
    __shared__ float t0[32][33], t1[32][33];
    int lb = blockIdx.x * 32, mb = blockIdx.y * 32;
    int x = threadIdx.x, y = threadIdx.y;
    for (int yy = y; yy < 32; yy += 8) {
        t0[yy][x] = Are[(size_t)(mb+yy)*Ldim + lb + x];
        t1[yy][x] = Aim[(size_t)(mb+yy)*Ldim + lb + x];
    }
    __syncthreads();
    for (int yy = y; yy < 32; yy += 8) {
        g_Atre[(size_t)(lb+yy)*Mdim + mb + x] = t0[x][yy];
        g_Atim[(size_t)(lb+yy)*Mdim + mb + x] = t1[x][yy];
    }
}

// ---------------- q, d, v, u ----------------
__global__ __launch_bounds__(256)
void qduv_kernel(const float* __restrict__ gamma, const float* __restrict__ delta) {
    int wid = threadIdx.x >> 5, lane = threadIdx.x & 31;
    int l = blockIdx.x * 8 + wid;
    const float4* zr  = (const float4*)(g_Ztre + (size_t)l*Mdim);
    const float4* zi  = (const float4*)(g_Ztim + (size_t)l*Mdim);
    const float4* gr  = (const float4*)(g_GZre + (size_t)l*Mdim);
    const float4* gi  = (const float4*)(g_GZim + (size_t)l*Mdim);
    const float4* ar  = (const float4*)(g_Atre + (size_t)l*Mdim);
    const float4* ai  = (const float4*)(g_Atim + (size_t)l*Mdim);
    float q = 0.f, d = 0.f;
    #pragma unroll
    for (int it = 0; it < 2; it++) {
        int k = lane + it*32;
        float4 a = zr[k], b = zi[k], c = gr[k], e = gi[k], f = ar[k], g2 = ai[k];
        q += a.x*c.x + a.y*c.y + a.z*c.z + a.w*c.w
           + b.x*e.x + b.y*e.y + b.z*e.z + b.w*e.w;
        d += a.x*f.x + a.y*f.y + a.z*f.z + a.w*f.w
           - (b.x*g2.x + b.y*g2.y + b.z*g2.z + b.w*g2.w);
    }
    q = warp_sum(q); d = warp_sum(d);
    if (lane == 0) {
        float v = q / (d + 1e-12f);
        float dl = 1.f / (1.f + expf(-delta[0]));
        float p = gamma[l];
        g_v[l] = v;
        g_u[l] = p + dl * (v - p);
    }
}

// ---------------- LayerNorm + kv stats ----------------
__global__ void ln_kernel(const float* __restrict__ ln_w, const float* __restrict__ ln_b,
                          const float* __restrict__ in_w, const float* __restrict__ in_b)
{
    __shared__ float red[512];
    __shared__ float s_mu, s_inv;
    int t = threadIdx.x;
    float s = 0.f;
    for (int i = t; i < Ldim; i += 512) s += g_u[i];
    red[t] = s; __syncthreads();
    for (int o = 256; o > 0; o >>= 1) { if (t < o) red[t] += red[t+o]; __syncthreads(); }
    if (t == 0) s_mu = red[0] / (float)Ldim;
    __syncthreads();
    float mu = s_mu, s2 = 0.f;
    for (int i = t; i < Ldim; i += 512) { float d = g_u[i] - mu; s2 += d*d; }
    red[t] = s2; __syncthreads();
    for (int o = 256; o > 0; o >>= 1) { if (t < o) red[t] += red[t+o]; __syncthreads(); }
    if (t == 0) s_inv = rsqrtf(red[0] / (float)Ldim + 1e-5f);
    __syncthreads();
    float inv = s_inv;
    float w1 = in_w[1], b1 = in_b[1];
    float kmin = 3.4e38f, kmax = -3.4e38f;
    for (int i = t; i < Ldim; i += 512) {
        float up = (g_u[i] - mu) * inv * ln_w[i] + ln_b[i];
        g_up[i] = up;
        float k2 = (up * w1 + b1) * LOG2E_F;
        kmin = fminf(kmin, k2); kmax = fmaxf(kmax, k2);
    }
    red[t] = kmax; __syncthreads();
    for (int o = 256; o > 0; o >>= 1) { if (t < o) red[t] = fmaxf(red[t], red[t+o]); __syncthreads(); }
    if (t == 0) g_scal[2] = red[0];
    __syncthreads();
    red[t] = kmin; __syncthreads();
    for (int o = 256; o > 0; o >>= 1) { if (t < o) red[t] = fminf(red[t], red[t+o]); __syncthreads(); }
    if (t == 0) g_scal[1] = red[0];
}

// ---------------- attention (rank-1 softmax) ----------------
__global__ __launch_bounds__(256)
void attn_kernel(const float* __restrict__ in_w, const float* __restrict__ in_b,
                 const float* __restrict__ out_w, const float* __restrict__ out_b)
{
    __shared__ float skv2[Ldim];
    __shared__ float svv[Ldim];
    int t = threadIdx.x;
    float w0 = in_w[0], b0 = in_b[0];
    float w1 = in_w[1], b1 = in_b[1];
    float w2 = in_w[2], b2 = in_b[2];
    for (int j = t; j < Ldim; j += 256) {
        float up = g_up[j];
        skv2[j] = (up * w1 + b1) * LOG2E_F;
        svv[j]  = up * w2 + b2;
    }
    __syncthreads();
    float k2min = g_scal[1], k2max = g_scal[2];
    float ow = out_w[0], ob = out_b[0];
    int warp = t >> 5, lane = t & 31;
    #pragma unroll
    for (int r = 0; r < 4; r++) {
        int i = blockIdx.x * 32 + warp * 4 + r;
        float qv = g_up[i] * w0 + b0;
        float m2 = (qv >= 0.f) ? qv * k2max : qv * k2min;
        float den = 0.f, num = 0.f;
        for (int j = lane; j < Ldim; j += 32) {
            float arg = qv * skv2[j] - m2;
            float e;
            asm("ex2.approx.f32 %0, %1;" : "=f"(e) : "f"(arg));
            den += e;
            num = fmaf(e, svv[j], num);
        }
        den = warp_sum(den); num = warp_sum(num);
        if (lane == 0) g_attn[i] = (num / den) * ow + ob;
    }
}

// ---------------- gate matvec (sigmoid) ----------------
__global__ __launch_bounds__(256)
void gate_kernel(const float* __restrict__ W, const float* __restrict__ gb)
{
    int warp = threadIdx.x >> 5, lane = threadIdx.x & 31;
    int i = blockIdx.x * 8 + warp;
    const float4* Wr = (const float4*)(W + (size_t)i * Ldim);
    const float4* U4 = (const float4*)g_u;
    float acc = 0.f;
    for (int k = lane; k < Ldim/4; k += 32) {
        float4 w4 = Wr[k]; float4 u4 = U4[k];
        acc += w4.x*u4.x + w4.y*u4.y + w4.z*u4.z + w4.w*u4.w;
    }
    acc = warp_sum(acc);
    if (lane == 0) {
        float z = acc + gb[i];
        g_gate[i] = 1.f / (1.f + expf(-z));
    }
}
// ---------------- final combine ----------------
__global__ void combine_kernel(const float* __restrict__ gamma,
                               const float* __restrict__ lmbda, float* __restrict__ out)
{
    int i = blockIdx.x * 256 + threadIdx.x;
    float g = g_gate[i];
    float s = g * g_v[i] + (1.f - g) * gamma[i] + g_attn[i] - lmbda[0];
    out[i] = fmaxf(s, 0.f);
}

// ---------------- launch ----------------
extern "C" void kernel_launch(void* const* d_in, const int* in_sizes, int n_in,
                              void* d_out, int out_size)
{
    const float* gamma  = (const float*)d_in[0];
    const float* A_re   = (const float*)d_in[1];
    const float* A_im   = (const float*)d_in[2];
    const float* X_re   = (const float*)d_in[3];
    const float* X_im   = (const float*)d_in[4];
    const float* ln_w   = (const float*)d_in[5];
    const float* ln_b   = (const float*)d_in[6];
    const float* in_w   = (const float*)d_in[7];
    const float* in_b   = (const float*)d_in[8];
    const float* out_w  = (const float*)d_in[9];
    const float* out_b  = (const float*)d_in[10];
    const float* gate_W = (const float*)d_in[11];
    const float* gate_b = (const float*)d_in[12];
    const float* delta  = (const float*)d_in[13];
    const float* lmbda  = (const float*)d_in[14];
    float* out = (float*)d_out;

    static cudaStream_t s1 = nullptr;
    static cudaEvent_t evFork, evZtA, evZtB, evJoin, evU, evGate;
    if (!s1) {
        cudaStreamCreateWithFlags(&s1, cudaStreamNonBlocking);
        cudaEventCreateWithFlags(&evFork, cudaEventDisableTiming);
        cudaEventCreateWithFlags(&evZtA, cudaEventDisableTiming);
        cudaEventCreateWithFlags(&evZtB, cudaEventDisableTiming);
        cudaEventCreateWithFlags(&evJoin, cudaEventDisableTiming);
        cudaEventCreateWithFlags(&evU,   cudaEventDisableTiming);
        cudaEventCreateWithFlags(&evGate,cudaEventDisableTiming);
        cudaFuncSetAttribute(cgemm_mma, cudaFuncAttributeMaxDynamicSharedMemorySize, ENG_SMEM2);
    }

    float *Rre,*Rim,*Gre,*Gim,*Xare,*Xaim,*Xbre,*Xbim,*Pre,*Pim;
    float *pre,*pim,*Atre,*Atim,*Ztre,*Ztim,*GZre,*GZim;
    cudaGetSymbolAddress((void**)&Rre,  g_Rre);   cudaGetSymbolAddress((void**)&Rim,  g_Rim);
    cudaGetSymbolAddress((void**)&Gre,  g_Gre);   cudaGetSymbolAddress((void**)&Gim,  g_Gim);
    cudaGetSymbolAddress((void**)&Xare, g_Xa_re); cudaGetSymbolAddress((void**)&Xaim, g_Xa_im);
    cudaGetSymbolAddress((void**)&Xbre, g_Xb_re); cudaGetSymbolAddress((void**)&Xbim, g_Xb_im);
    cudaGetSymbolAddress((void**)&Pre,  g_P_re);  cudaGetSymbolAddress((void**)&Pim,  g_P_im);
    cudaGetSymbolAddress((void**)&pre,  g_part_re); cudaGetSymbolAddress((void**)&pim, g_part_im);
    cudaGetSymbolAddress((void**)&Atre, g_Atre);  cudaGetSymbolAddress((void**)&Atim, g_Atim);
    cudaGetSymbolAddress((void**)&Ztre, g_Ztre);  cudaGetSymbolAddress((void**)&Ztim, g_Ztim);
    cudaGetSymbolAddress((void**)&GZre, g_GZre);  cudaGetSymbolAddress((void**)&GZim, g_GZim);

    // fork: s1 handles the q-chain engine work (slots 32..47)
    transposeA<<<dim3(128, 8), dim3(32, 8)>>>(A_re, A_im);
    cudaEventRecord(evFork, 0);
    cudaStreamWaitEvent(s1, evFork, 0);
    cgemm_mma<<<dim3(2,2,32), 256, ENG_SMEM2, s1>>>(X_re, X_im, Tdim, X_re, X_im, Tdim,
                                                    pre + (size_t)32*65536, pim + (size_t)32*65536,
                                                    Mdim, 128, 1, nullptr, 65536, 0);
    reduce_RG<<<256, 256, 0, s1>>>(Gre, Gim, 16, 0, 32);

    // s0: R chain
    csyrk_big<<<dim3(6,1,16), 256>>>(pre, pim, A_re, A_im, gamma, Ldim, 256);
    reduce_RG<<<256, 256>>>(Rre, Rim, 16, 1, 0);
    mirror_R<<<64, 256>>>();
    trace_alpha<<<1, 1024>>>();
    init_X1<<<256, 256>>>(Xare, Xaim);

    // Newton: iter0 explicit, iters1-5 with fused-newton GEMM1 (materializes Xn)
    float *Xc_re = Xare, *Xc_im = Xaim, *Xn_re = Xbre, *Xn_im = Xbim;
    cgemm_big<<<dim3(4,2,16), 256>>>(pre, pim, Rre, Rim, Mdim,
                                     Xc_re, Xc_im, Mdim, 16, 65536, 0);
    cgemm_fsum<<<dim3(4,2,16), 256>>>(pre + (size_t)16*65536, pim + (size_t)16*65536,
                                      Xc_re, Xc_im, Mdim, pre, pim, Mdim, 16, 16, 65536);
    for (int it = 1; it < 6; ++it) {
        cgemm_bfn<<<dim3(4,2,16), 256>>>(pre, pim, Rre, Rim, Mdim,
                                         Xc_re, Xc_im, Mdim, Xn_re, Xn_im);
        cgemm_fsum<<<dim3(4,2,16), 256>>>(pre + (size_t)16*65536, pim + (size_t)16*65536,
                                          Xn_re, Xn_im, Mdim, pre, pim, Mdim, 16, 16, 65536);
        float* tmp;
        tmp = Xc_re; Xc_re = Xn_re; Xn_re = tmp;
        tmp = Xc_im; Xc_im = Xn_im; Xn_im = tmp;
    }
    reduce_newton<<<256, 256>>>(Xn_re, Xn_im, Xc_re, Xc_im, 16, 16);
    symm_conj<<<256, 256>>>(Xn_re, Xn_im, Pre, Pim);

    // Zt in two halves; GZt pipelined on s1 (tensor pipe overlaps FFMA)
    cgemm_big<<<dim3(4,16,1), 256>>>(Ztre, Ztim, Atre, Atim, Mdim,
                                     Pre, Pim, Mdim, 256, 0, 0);
    cudaEventRecord(evZtA, 0);
    cgemm_big<<<dim3(4,16,1), 256>>>(Ztre, Ztim, Atre, Atim, Mdim,
                                     Pre, Pim, Mdim, 256, 0, 16);
    cudaEventRecord(evZtB, 0);
    cudaStreamWaitEvent(s1, evZtA, 0);
    cgemm_mma<<<dim3(2,16,2), 256, ENG_SMEM2, s1>>>(Ztre, Ztim, Mdim, Gre, Gim, Mdim,
                                                    GZre, GZim, Mdim, 256, 0, nullptr, 0, 0);
    cudaStreamWaitEvent(s1, evZtB, 0);
    cgemm_mma<<<dim3(2,16,2), 256, ENG_SMEM2, s1>>>(Ztre, Ztim, Mdim, Gre, Gim, Mdim,
                                                    GZre, GZim, Mdim, 256, 0, nullptr, 0, 16);
    cudaEventRecord(evJoin, s1);
    cudaStreamWaitEvent(0, evJoin, 0);

    // tail: gate matvec overlaps ln+attn
    qduv_kernel<<<512, 256>>>(gamma, delta);
    cudaEventRecord(evU, 0);
    cudaStreamWaitEvent(s1, evU, 0);
    gate_kernel<<<512, 256, 0, s1>>>(gate_W, gate_b);
    cudaEventRecord(evGate, s1);
    ln_kernel<<<1, 512>>>(ln_w, ln_b, in_w, in_b);
    attn_kernel<<<128, 256>>>(in_w, in_b, out_w, out_b);
    cudaStreamWaitEvent(0, evGate, 0);
    combine_kernel<<<16, 256>>>(gamma, lmbda, out);
}

// round 16
// speedup vs baseline: 1.2957x; 1.2957x over previous
#include <cuda_runtime.h>
#include <cuda_bf16.h>
#include <math.h>
#include <stdint.h>

#define Mdim 256
#define Ldim 4096
#define Tdim 2048
#define LOG2E_F 1.4426950408889634f

// ---------------- device scratch ----------------
__device__ float g_Rre[Mdim*Mdim], g_Rim[Mdim*Mdim];
__device__ float g_Gre[Mdim*Mdim], g_Gim[Mdim*Mdim];
__device__ float g_Xa_re[Mdim*Mdim], g_Xa_im[Mdim*Mdim];
__device__ float g_Xb_re[Mdim*Mdim], g_Xb_im[Mdim*Mdim];
__device__ float g_P_re[Mdim*Mdim],  g_P_im[Mdim*Mdim];
__device__ float g_part_re[32*Mdim*Mdim], g_part_im[32*Mdim*Mdim];
__device__ float g_Atre[Ldim*Mdim], g_Atim[Ldim*Mdim];
__device__ float g_Ztre[Ldim*Mdim], g_Ztim[Ldim*Mdim];
__device__ float g_GZre[Ldim*Mdim], g_GZim[Ldim*Mdim];
__device__ float g_v[Ldim], g_u[Ldim], g_up[Ldim], g_attn[Ldim];
__device__ float g_scal[4];   // [0]=alpha  [1]=kv2min [2]=kv2max

__device__ __forceinline__ float warp_sum(float v) {
    #pragma unroll
    for (int o = 16; o > 0; o >>= 1) v += __shfl_xor_sync(0xffffffffu, v, o);
    return v;
}

// ---------------- smem helpers ----------------
__device__ __forceinline__ uint32_t smem_u32(const void* p) {
    uint32_t a;
    asm("{ .reg .u64 t; cvta.to.shared.u64 t, %1; cvt.u32.u64 %0, t; }" : "=r"(a) : "l"(p));
    return a;
}
__device__ __forceinline__ uint32_t lds32(uint32_t a) {
    uint32_t v;
    asm volatile("ld.shared.b32 %0, [%1];" : "=r"(v) : "r"(a));
    return v;
}
__device__ __forceinline__ void sts128(uint32_t a, uint32_t x, uint32_t y,
                                       uint32_t z, uint32_t w) {
    asm volatile("st.shared.v4.b32 [%0], {%1,%2,%3,%4};"
                 :: "r"(a), "r"(x), "r"(y), "r"(z), "r"(w) : "memory");
}
__device__ __forceinline__ uint32_t cvt_tf32(float x) {
    uint32_t r;
    asm("cvt.rna.tf32.f32 %0, %1;" : "=r"(r) : "f"(x));
    return r;
}
#define MMAT32(d, a, b) \
    asm volatile("mma.sync.aligned.m16n8k8.row.col.f32.tf32.tf32.f32 " \
        "{%0,%1,%2,%3},{%4,%5,%6,%7},{%8,%9},{%0,%1,%2,%3};" \
        : "+f"((d)[0]), "+f"((d)[1]), "+f"((d)[2]), "+f"((d)[3]) \
        : "r"((a)[0]), "r"((a)[1]), "r"((a)[2]), "r"((a)[3]), "r"((b)[0]), "r"((b)[1]))

#define PITCHB 144
#define PLSZ   18432
#define ENG_SMEM2 (8*PLSZ)

// convert one 128x32 fp32 tile -> 2 tf32 split planes in smem (sign/weight folded)
__device__ __forceinline__ void conv_tile2(uint32_t sa, int tbase,
                                           const float* __restrict__ src, int row0, int ld,
                                           int k0, const float* __restrict__ w, float sgn)
{
    int tid = threadIdx.x;
    uint32_t p0 = sa + tbase*PLSZ;
    uint32_t p1 = p0 + PLSZ;
    #pragma unroll
    for (int p = 0; p < 4; p++) {
        int idx = tid + p*256;
        int row = idx >> 3, c4 = idx & 7;
        float4 v = *(const float4*)(src + (size_t)(row0+row)*ld + k0 + c4*4);
        if (w) {
            float4 wv = *(const float4*)(w + k0 + c4*4);
            v.x *= wv.x; v.y *= wv.y; v.z *= wv.z; v.w *= wv.w;
        }
        v.x *= sgn; v.y *= sgn; v.z *= sgn; v.w *= sgn;
        uint32_t h0 = cvt_tf32(v.x), h1 = cvt_tf32(v.y);
        uint32_t h2 = cvt_tf32(v.z), h3 = cvt_tf32(v.w);
        uint32_t m0 = cvt_tf32(v.x - __uint_as_float(h0));
        uint32_t m1 = cvt_tf32(v.y - __uint_as_float(h1));
        uint32_t m2 = cvt_tf32(v.z - __uint_as_float(h2));
        uint32_t m3 = cvt_tf32(v.w - __uint_as_float(h3));
        uint32_t off = row*PITCHB + c4*16;
        sts128(p0 + off, h0, h1, h2, h3);
        sts128(p1 + off, m0, m1, m2, m3);
    }
}

// ============================================================================
// split-tf32 complex GEMM via mma.sync m16n8k8 (q-chain ONLY — G and GZt)
// ============================================================================
__global__ __launch_bounds__(256, 1)
void cgemm_mma(const float* __restrict__ Pre, const float* __restrict__ Pim, int ldp,
               const float* __restrict__ Qre, const float* __restrict__ Qim, int ldq,
               float* __restrict__ Cre, float* __restrict__ Cim, int ldc,
               int Kper, int conj, const float* __restrict__ w, int partElems)
{
    extern __shared__ char dsm[];
    uint32_t sa = smem_u32(dsm);
    int tid = threadIdx.x;
    int wid = tid >> 5, lane = tid & 31;
    int g = lane >> 2, t4 = lane & 3;
    int warpM = wid >> 2, warpN = wid & 3;
    int i0 = blockIdx.y * 128, j0 = blockIdx.x * 128;
    int plane = blockIdx.z & 1, ks = blockIdx.z >> 1;

    const float* A0 = (conj && plane) ? Pim : Pre;
    const float* A1 = (conj && plane) ? Pre : Pim;
    float s1 = ((conj && plane) || (!conj && !plane)) ? -1.f : 1.f;
    const float* B0 = (!conj && plane) ? Qim : Qre;
    const float* B1 = (!conj && plane) ? Qre : Qim;

    float acc[4][4][4] = {};

    int nCh = Kper >> 5;
    for (int ch = 0; ch < nCh; ch++) {
        int k0 = ks * Kper + ch * 32;
        conv_tile2(sa, 0, A0, i0, ldp, k0, w, 1.f);
        conv_tile2(sa, 2, A1, i0, ldp, k0, w, s1);
        conv_tile2(sa, 4, B0, j0, ldq, k0, (const float*)0, 1.f);
        conv_tile2(sa, 6, B1, j0, ldq, k0, (const float*)0, 1.f);
        __syncthreads();

        const int ta[6] = {0, 0, 1, 2, 2, 3};
        const int tb[6] = {4, 5, 4, 6, 7, 6};
        #pragma unroll
        for (int ps = 0; ps < 6; ps++) {
            uint32_t ab = sa + ta[ps]*PLSZ;
            uint32_t bb = sa + tb[ps]*PLSZ;
            #pragma unroll
            for (int kk = 0; kk < 4; kk++) {
                uint32_t afr[4][4], bfr[4][2];
                #pragma unroll
                for (int am = 0; am < 4; am++) {
                    uint32_t r0 = ab + (warpM*64 + am*16 + g)*PITCHB + (kk*8 + t4)*4;
                    afr[am][0] = lds32(r0);
                    afr[am][1] = lds32(r0 + 8*PITCHB);
                    afr[am][2] = lds32(r0 + 16);
                    afr[am][3] = lds32(r0 + 8*PITCHB + 16);
                }
                #pragma unroll
                for (int bn = 0; bn < 4; bn++) {
                    uint32_t r0 = bb + (warpN*32 + bn*8 + g)*PITCHB + (kk*8 + t4)*4;
                    bfr[bn][0] = lds32(r0);
                    bfr[bn][1] = lds32(r0 + 16);
                }
                #pragma unroll
                for (int am = 0; am < 4; am++)
                    #pragma unroll
                    for (int bn = 0; bn < 4; bn++)
                        MMAT32(acc[am][bn], afr[am], bfr[bn]);
            }
        }
        __syncthreads();
    }

    float* dst = plane ? Cim : Cre;
    size_t zoff = (size_t)ks * partElems;
    #pragma unroll
    for (int am = 0; am < 4; am++) {
        #pragma unroll
        for (int bn = 0; bn < 4; bn++) {
            int r = i0 + warpM*64 + am*16 + g;
            int c = j0 + warpN*32 + bn*8 + 2*t4;
            float2 v0 = make_float2(acc[am][bn][0], acc[am][bn][1]);
            float2 v1 = make_float2(acc[am][bn][2], acc[am][bn][3]);
            *(float2*)(dst + zoff + (size_t)r*ldc + c) = v0;
            *(float2*)(dst + zoff + (size_t)(r+8)*ldc + c) = v1;
        }
    }
}

// ============================================================================
// High-ILP fp32 SIMT complex GEMMs: BM=128, BN=64, BK=16, TM=8, TN=4.
// ============================================================================
#define BBM 128
#define BBN 64
#define BBK 16

// Hermitian csyrk: 6 lower/diagonal tiles of C = (A*diag(w)) A^H.
__global__ __launch_bounds__(256)
void csyrk_big(float* __restrict__ Pre, float* __restrict__ Pim,
               const float* __restrict__ Are, const float* __restrict__ Aim,
               const float* __restrict__ w, int lda, int kChunk)
{
    __shared__ float as_re[BBK][BBM+4], as_im[BBK][BBM+4];
    __shared__ float bs_re[BBK][BBN+4], bs_im[BBK][BBN+4];
    const int tbi[6] = {0, 0, 128, 128, 128, 128};
    const int tbj[6] = {0, 64, 0, 64, 128, 192};
    int i0 = tbi[blockIdx.x], j0 = tbj[blockIdx.x];
    int k0 = blockIdx.z * kChunk;
    int t  = threadIdx.x;
    int tx = t & 15, ty = t >> 4;
    int arow = t >> 2, ak4 = (t & 3) * 4;
    float cre[8][4] = {}, cim[8][4] = {};

    for (int kb = 0; kb < kChunk; kb += BBK) {
        int kbase = k0 + kb;
        float4 wv;
        if (w) wv = *(const float4*)(w + kbase + ak4);
        else   wv = make_float4(1.f, 1.f, 1.f, 1.f);
        #pragma unroll
        for (int r = 0; r < 2; r++) {
            int row = arow + r*64;
            float4 vr = *(const float4*)(Are + (size_t)(i0+row)*lda + kbase + ak4);
            float4 vi = *(const float4*)(Aim + (size_t)(i0+row)*lda + kbase + ak4);
            as_re[ak4+0][row] = vr.x*wv.x; as_re[ak4+1][row] = vr.y*wv.y;
            as_re[ak4+2][row] = vr.z*wv.z; as_re[ak4+3][row] = vr.w*wv.w;
            as_im[ak4+0][row] = vi.x*wv.x; as_im[ak4+1][row] = vi.y*wv.y;
            as_im[ak4+2][row] = vi.z*wv.z; as_im[ak4+3][row] = vi.w*wv.w;
        }
        {
            int col = t >> 2;
            float4 vr = *(const float4*)(Are + (size_t)(j0+col)*lda + kbase + ak4);
            float4 vi = *(const float4*)(Aim + (size_t)(j0+col)*lda + kbase + ak4);
            bs_re[ak4+0][col] = vr.x; bs_re[ak4+1][col] = vr.y;
            bs_re[ak4+2][col] = vr.z; bs_re[ak4+3][col] = vr.w;
            bs_im[ak4+0][col] = vi.x; bs_im[ak4+1][col] = vi.y;
            bs_im[ak4+2][col] = vi.z; bs_im[ak4+3][col] = vi.w;
        }
        __syncthreads();
        #pragma unroll
        for (int kk = 0; kk < BBK; kk++) {
            float ar[8], ai[8], br[4], bi[4];
            #pragma unroll
            for (int i = 0; i < 8; i++) { ar[i] = as_re[kk][ty*8+i]; ai[i] = as_im[kk][ty*8+i]; }
            #pragma unroll
            for (int j = 0; j < 4; j++) { br[j] = bs_re[kk][tx*4+j]; bi[j] = bs_im[kk][tx*4+j]; }
            #pragma unroll
            for (int i = 0; i < 8; i++)
                #pragma unroll
                for (int j = 0; j < 4; j++) {
                    cre[i][j] += ar[i]*br[j];
                    cre[i][j] += ai[i]*bi[j];
                    cim[i][j] += ai[i]*br[j];
                    cim[i][j] -= ar[i]*bi[j];
                }
        }
        __syncthreads();
    }
    size_t off = (size_t)blockIdx.z * (Mdim*Mdim);
    #pragma unroll
    for (int i = 0; i < 8; i++) {
        int gi = i0 + ty*8 + i, gj = j0 + tx*4;
        *(float4*)(Pre + off + (size_t)gi*Mdim + gj) = make_float4(cre[i][0], cre[i][1], cre[i][2], cre[i][3]);
        *(float4*)(Pim + off + (size_t)gi*Mdim + gj) = make_float4(cim[i][0], cim[i][1], cim[i][2], cim[i][3]);
    }
}

// nn variant: C[i,j] = sum_k A[i,k]*B[k,j]
__global__ __launch_bounds__(256)
void cgemm_big(float* __restrict__ Cre, float* __restrict__ Cim,
               const float* __restrict__ Are, const float* __restrict__ Aim, int lda,
               const float* __restrict__ Bre, const float* __restrict__ Bim, int ldb,
               int kChunk, int MNpart)
{
    __shared__ float as_re[BBK][BBM+4], as_im[BBK][BBM+4];
    __shared__ float bs_re[BBK][BBN+4], bs_im[BBK][BBN+4];
    int i0 = blockIdx.y * BBM, j0 = blockIdx.x * BBN;
    int k0 = blockIdx.z * kChunk;
    int t  = threadIdx.x;
    int tx = t & 15, ty = t >> 4;
    int arow = t >> 2, ak4 = (t & 3) * 4;
    int bk = t >> 4, bc4 = (t & 15) * 4;
    float cre[8][4] = {}, cim[8][4] = {};

    for (int kb = 0; kb < kChunk; kb += BBK) {
        int kbase = k0 + kb;
        #pragma unroll
        for (int r = 0; r < 2; r++) {
            int row = arow + r*64;
            float4 vr = *(const float4*)(Are + (size_t)(i0+row)*lda + kbase + ak4);
            float4 vi = *(const float4*)(Aim + (size_t)(i0+row)*lda + kbase + ak4);
            as_re[ak4+0][row] = vr.x; as_re[ak4+1][row] = vr.y;
            as_re[ak4+2][row] = vr.z; as_re[ak4+3][row] = vr.w;
            as_im[ak4+0][row] = vi.x; as_im[ak4+1][row] = vi.y;
            as_im[ak4+2][row] = vi.z; as_im[ak4+3][row] = vi.w;
        }
        {
            float4 vr = *(const float4*)(Bre + (size_t)(kbase+bk)*ldb + j0 + bc4);
            float4 vi = *(const float4*)(Bim + (size_t)(kbase+bk)*ldb + j0 + bc4);
            *(float4*)&bs_re[bk][bc4] = vr;
            *(float4*)&bs_im[bk][bc4] = vi;
        }
        __syncthreads();
        #pragma unroll
        for (int kk = 0; kk < BBK; kk++) {
            float ar[8], ai[8], br[4], bi[4];
            #pragma unroll
            for (int i = 0; i < 8; i++) { ar[i] = as_re[kk][ty*8+i]; ai[i] = as_im[kk][ty*8+i]; }
            #pragma unroll
            for (int j = 0; j < 4; j++) { br[j] = bs_re[kk][tx*4+j]; bi[j] = bs_im[kk][tx*4+j]; }
            #pragma unroll
            for (int i = 0; i < 8; i++)
                #pragma unroll
                for (int j = 0; j < 4; j++) {
                    cre[i][j] += ar[i]*br[j];
                    cre[i][j] -= ai[i]*bi[j];
                    cim[i][j] += ar[i]*bi[j];
                    cim[i][j] += ai[i]*br[j];
                }
        }
        __syncthreads();
    }
    size_t off = (size_t)blockIdx.z * MNpart;
    #pragma unroll
    for (int i = 0; i < 8; i++) {
        int gi = i0 + ty*8 + i, gj = j0 + tx*4;
        *(float4*)(Cre + off + (size_t)gi*ldb + gj) = make_float4(cre[i][0], cre[i][1], cre[i][2], cre[i][3]);
        *(float4*)(Cim + off + (size_t)gi*ldb + gj) = make_float4(cim[i][0], cim[i][1], cim[i][2], cim[i][3]);
    }
}

// Newton GEMM1 with fused B = 2*Xbase - sum(parts 16..31) (bit-identical to
// reduce_newton) + Xn materialization by blockIdx.y==0 CTAs. A = R. grid (4,2,16).
__global__ __launch_bounds__(256)
void cgemm_bfn(float* __restrict__ Cre, float* __restrict__ Cim,
               const float* __restrict__ Are, const float* __restrict__ Aim, int lda,
               const float* __restrict__ Xbre, const float* __restrict__ Xbim, int ldb,
               float* __restrict__ XnRe, float* __restrict__ XnIm)
{
    __shared__ float as_re[BBK][BBM+4], as_im[BBK][BBM+4];
    __shared__ float bs_re[BBK][BBN+4], bs_im[BBK][BBN+4];
    int i0 = blockIdx.y * BBM, j0 = blockIdx.x * BBN;
    int kbase = blockIdx.z * BBK;
    int t  = threadIdx.x;
    int tx = t & 15, ty = t >> 4;
    int arow = t >> 2, ak4 = (t & 3) * 4;
    int bk = t >> 4, bc4 = (t & 15) * 4;
    float cre[8][4] = {}, cim[8][4] = {};

    #pragma unroll
    for (int r = 0; r < 2; r++) {
        int row = arow + r*64;
        float4 vr = *(const float4*)(Are + (size_t)(i0+row)*lda + kbase + ak4);
        float4 vi = *(const float4*)(Aim + (size_t)(i0+row)*lda + kbase + ak4);
        as_re[ak4+0][row] = vr.x; as_re[ak4+1][row] = vr.y;
        as_re[ak4+2][row] = vr.z; as_re[ak4+3][row] = vr.w;
        as_im[ak4+0][row] = vi.x; as_im[ak4+1][row] = vi.y;
        as_im[ak4+2][row] = vi.z; as_im[ak4+3][row] = vi.w;
    }
    {
        size_t eoff = (size_t)(kbase+bk)*ldb + j0 + bc4;
        float4 xr = *(const float4*)(Xbre + eoff);
        float4 xi = *(const float4*)(Xbim + eoff);
        float4 sr = make_float4(0.f,0.f,0.f,0.f), si = make_float4(0.f,0.f,0.f,0.f);
        for (int z = 16; z < 32; z++) {
            float4 pr = *(const float4*)(g_part_re + (size_t)z*65536 + eoff);
            float4 pi = *(const float4*)(g_part_im + (size_t)z*65536 + eoff);
            sr.x += pr.x; sr.y += pr.y; sr.z += pr.z; sr.w += pr.w;
            si.x += pi.x; si.y += pi.y; si.z += pi.z; si.w += pi.w;
        }
        float4 vr = make_float4(2.f*xr.x - sr.x, 2.f*xr.y - sr.y, 2.f*xr.z - sr.z, 2.f*xr.w - sr.w);
        float4 vi = make_float4(2.f*xi.x - si.x, 2.f*xi.y - si.y, 2.f*xi.z - si.z, 2.f*xi.w - si.w);
        *(float4*)&bs_re[bk][bc4] = vr;
        *(float4*)&bs_im[bk][bc4] = vi;
        if (blockIdx.y == 0) {
            *(float4*)(XnRe + eoff) = vr;
            *(float4*)(XnIm + eoff) = vi;
        }
    }
    __syncthreads();
    #pragma unroll
    for (int kk = 0; kk < BBK; kk++) {
        float ar[8], ai[8], br[4], bi[4];
        #pragma unroll
        for (int i = 0; i < 8; i++) { ar[i] = as_re[kk][ty*8+i]; ai[i] = as_im[kk][ty*8+i]; }
        #pragma unroll
        for (int j = 0; j < 4; j++) { br[j] = bs_re[kk][tx*4+j]; bi[j] = bs_im[kk][tx*4+j]; }
        #pragma unroll
        for (int i = 0; i < 8; i++)
            #pragma unroll
            for (int j = 0; j < 4; j++) {
                cre[i][j] += ar[i]*br[j];
                cre[i][j] -= ai[i]*bi[j];
                cim[i][j] += ar[i]*bi[j];
                cim[i][j] += ai[i]*br[j];
            }
    }
    __syncthreads();
    size_t off = (size_t)blockIdx.z * 65536;
    #pragma unroll
    for (int i = 0; i < 8; i++) {
        int gi = i0 + ty*8 + i, gj = j0 + tx*4;
        *(float4*)(Cre + off + (size_t)gi*ldb + gj) = make_float4(cre[i][0], cre[i][1], cre[i][2], cre[i][3]);
        *(float4*)(Cim + off + (size_t)gi*ldb + gj) = make_float4(cim[i][0], cim[i][1], cim[i][2], cim[i][3]);
    }
}

// nn variant with fused B-reduction (sum parts 0..SK-1, ascending)
__global__ __launch_bounds__(256)
void cgemm_fsum(float* __restrict__ Cre, float* __restrict__ Cim,
                const float* __restrict__ Are, const float* __restrict__ Aim, int lda,
                const float* __restrict__ Bpre, const float* __restrict__ Bpim, int ldb,
                int SK, int kChunk, int MNpart)
{
    __shared__ float as_re[BBK][BBM+4], as_im[BBK][BBM+4];
    __shared__ float bs_re[BBK][BBN+4], bs_im[BBK][BBN+4];
    int i0 = blockIdx.y * BBM, j0 = blockIdx.x * BBN;
    int k0 = blockIdx.z * kChunk;
    int t  = threadIdx.x;
    int tx = t & 15, ty = t >> 4;
    int arow = t >> 2, ak4 = (t & 3) * 4;
    int bk = t >> 4, bc4 = (t & 15) * 4;
    float cre[8][4] = {}, cim[8][4] = {};

    for (int kb = 0; kb < kChunk; kb += BBK) {
        int kbase = k0 + kb;
        #pragma unroll
        for (int r = 0; r < 2; r++) {
            int row = arow + r*64;
            float4 vr = *(const float4*)(Are + (size_t)(i0+row)*lda + kbase + ak4);
            float4 vi = *(const float4*)(Aim + (size_t)(i0+row)*lda + kbase + ak4);
            as_re[ak4+0][row] = vr.x; as_re[ak4+1][row] = vr.y;
            as_re[ak4+2][row] = vr.z; as_re[ak4+3][row] = vr.w;
            as_im[ak4+0][row] = vi.x; as_im[ak4+1][row] = vi.y;
            as_im[ak4+2][row] = vi.z; as_im[ak4+3][row] = vi.w;
        }
        {
            size_t eoff = (size_t)(kbase+bk)*ldb + j0 + bc4;
            float4 vr = make_float4(0.f,0.f,0.f,0.f), vi = make_float4(0.f,0.f,0.f,0.f);
            for (int z = 0; z < SK; z++) {
                float4 pr = *(const float4*)(Bpre + (size_t)z*65536 + eoff);
                float4 pi = *(const float4*)(Bpim + (size_t)z*65536 + eoff);
                vr.x += pr.x; vr.y += pr.y; vr.z += pr.z; vr.w += pr.w;
                vi.x += pi.x; vi.y += pi.y; vi.z += pi.z; vi.w += pi.w;
            }
            *(float4*)&bs_re[bk][bc4] = vr;
            *(float4*)&bs_im[bk][bc4] = vi;
        }
        __syncthreads();
        #pragma unroll
        for (int kk = 0; kk < BBK; kk++) {
            float ar[8], ai[8], br[4], bi[4];
            #pragma unroll
            for (int i = 0; i < 8; i++) { ar[i] = as_re[kk][ty*8+i]; ai[i] = as_im[kk][ty*8+i]; }
            #pragma unroll
            for (int j = 0; j < 4; j++) { br[j] = bs_re[kk][tx*4+j]; bi[j] = bs_im[kk][tx*4+j]; }
            #pragma unroll
            for (int i = 0; i < 8; i++)
                #pragma unroll
                for (int j = 0; j < 4; j++) {
                    cre[i][j] += ar[i]*br[j];
                    cre[i][j] -= ai[i]*bi[j];
                    cim[i][j] += ar[i]*bi[j];
                    cim[i][j] += ai[i]*br[j];
                }
        }
        __syncthreads();
    }
    size_t off = (size_t)blockIdx.z * MNpart;
    #pragma unroll
    for (int i = 0; i < 8; i++) {
        int gi = i0 + ty*8 + i, gj = j0 + tx*4;
        *(float4*)(Cre + off + (size_t)gi*ldb + gj) = make_float4(cre[i][0], cre[i][1], cre[i][2], cre[i][3]);
        *(float4*)(Cim + off + (size_t)gi*ldb + gj) = make_float4(cim[i][0], cim[i][1], cim[i][2], cim[i][3]);
    }
}

// ---------------- reduces ----------------
__global__ void reduce_RG(float* __restrict__ Cre, float* __restrict__ Cim, int SK, int ridge) {
    int e = blockIdx.x * 256 + threadIdx.x;
    float sr = 0.f, si = 0.f;
    for (int z = 0; z < SK; z++) { sr += g_part_re[z*65536 + e]; si += g_part_im[z*65536 + e]; }
    if (ridge && (e >> 8) == (e & 255)) sr += 0.01f;
    Cre[e] = sr; Cim[e] = si;
}
__global__ void mirror_R() {
    int e = blockIdx.x * 256 + threadIdx.x;
    int i = e >> 7, j = 128 + (e & 127);
    g_Rre[i*256 + j] =  g_Rre[j*256 + i];
    g_Rim[i*256 + j] = -g_Rim[j*256 + i];
}
__global__ void reduce_newton(float* __restrict__ Xnre, float* __restrict__ Xnim,
                              const float* __restrict__ Xre, const float* __restrict__ Xim,
                              int SK, int zoff)
{
    int e = blockIdx.x * 256 + threadIdx.x;
    float sr = 0.f, si = 0.f;
    for (int z = zoff; z < zoff + SK; z++) { sr += g_part_re[z*65536 + e]; si += g_part_im[z*65536 + e]; }
    Xnre[e] = 2.f*Xre[e] - sr;
    Xnim[e] = 2.f*Xim[e] - si;
}

// ---------------- alpha ; X1 = 2aI - a^2 R ----------------
__global__ void trace_alpha() {
    __shared__ float red[1024];
    __shared__ float s_fro;
    int t = threadIdx.x;
    float fro = 0.f;
    for (int e = t; e < 65536; e += 1024) {
        float a = g_Rre[e], b = g_Rim[e];
        fro += a*a + b*b;
    }
    red[t] = fro; __syncthreads();
    for (int o = 512; o > 0; o >>= 1) { if (t < o) red[t] += red[t+o]; __syncthreads(); }
    if (t == 0) s_fro = red[0];
    __syncthreads();
    float tr = 0.f;
    for (int i = t; i < 256; i += 1024) tr += g_Rre[i*257];
    red[t] = tr; __syncthreads();
    for (int o = 512; o > 0; o >>= 1) { if (t < o) red[t] += red[t+o]; __syncthreads(); }
    if (t == 0) g_scal[0] = red[0] / s_fro;
}
__global__ void init_X1(float* __restrict__ Xre, float* __restrict__ Xim) {
    int e = blockIdx.x * 256 + threadIdx.x;
    int i = e >> 8, j = e & 255;
    float a = g_scal[0];
    float a2 = a * a;
    Xre[e] = -a2 * g_Rre[e] + ((i == j) ? 2.f*a : 0.f);
    Xim[e] = -a2 * g_Rim[e];
}

// ---------------- Bc = conj(symmetrize(Rinv)) ----------------
__global__ void symm_conj(const float* __restrict__ Xre, const float* __restrict__ Xim,
                          float* __restrict__ Bre, float* __restrict__ Bim) {
    int e = blockIdx.x * 256 + threadIdx.x;
    int i = e >> 8, j = e & 255;
    Bre[e] = 0.5f * (Xre[i*256 + j] + Xre[j*256 + i]);
    Bim[e] = 0.5f * (Xim[j*256 + i] - Xim[i*256 + j]);
}

// ---------------- transpose A -> At [L][M] ----------------
__global__ void transposeA(const float* __restrict__ Are, const float* __restrict__ Aim) {
    __shared__ float t0[32][33], t1[32][33];
    int lb = blockIdx.x * 32, mb = blockIdx.y * 32;
    int x = threadIdx.x, y = threadIdx.y;
    for (int yy = y; yy < 32; yy += 8) {
        t0[yy][x] = Are[(size_t)(mb+yy)*Ldim + lb + x];
        t1[yy][x] = Aim[(size_t)(mb+yy)*Ldim + lb + x];
    }
    __syncthreads();
    for (int yy = y; yy < 32; yy += 8) {
        g_Atre[(size_t)(lb+yy)*Mdim + mb + x] = t0[x][yy];
        g_Atim[(size_t)(lb+yy)*Mdim + mb + x] = t1[x][yy];
    }
}

// ---------------- q, d, v, u ----------------
__global__ __launch_bounds__(256)
void qduv_kernel(const float* __restrict__ gamma, const float* __restrict__ delta) {
    int wid = threadIdx.x >> 5, lane = threadIdx.x & 31;
    int l = blockIdx.x * 8 + wid;
    const float4* zr  = (const float4*)(g_Ztre + (size_t)l*Mdim);
    const float4* zi  = (const float4*)(g_Ztim + (size_t)l*Mdim);
    const float4* gr  = (const float4*)(g_GZre + (size_t)l*Mdim);
    const float4* gi  = (const float4*)(g_GZim + (size_t)l*Mdim);
    const float4* ar  = (const float4*)(g_Atre + (size_t)l*Mdim);
    const float4* ai  = (const float4*)(g_Atim + (size_t)l*Mdim);
    float q = 0.f, d = 0.f;
    #pragma unroll
    for (int it = 0; it < 2; it++) {
        int k = lane + it*32;
        float4 a = zr[k], b = zi[k], c = gr[k], e = gi[k], f = ar[k], g2 = ai[k];
        q += a.x*c.x + a.y*c.y + a.z*c.z + a.w*c.w
           + b.x*e.x + b.y*e.y + b.z*e.z + b.w*e.w;
        d += a.x*f.x + a.y*f.y + a.z*f.z + a.w*f.w
           - (b.x*g2.x + b.y*g2.y + b.z*g2.z + b.w*g2.w);
    }
    q = warp_sum(q); d = warp_sum(d);
    if (lane == 0) {
        float v = q / (d + 1e-12f);
        float dl = 1.f / (1.f + expf(-delta[0]));
        float p = gamma[l];
        g_v[l] = v;
        g_u[l] = p + dl * (v - p);
    }
}

// ---------------- LayerNorm + kv stats ----------------
__global__ void ln_kernel(const float* __restrict__ ln_w, const float* __restrict__ ln_b,
                          const float* __restrict__ in_w, const float* __restrict__ in_b)
{
    __shared__ float red[512];
    __shared__ float s_mu, s_inv;
    int t = threadIdx.x;
    float s = 0.f;
    for (int i = t; i < Ldim; i += 512) s += g_u[i];
    red[t] = s; __syncthreads();
    for (int o = 256; o > 0; o >>= 1) { if (t < o) red[t] += red[t+o]; __syncthreads(); }
    if (t == 0) s_mu = red[0] / (float)Ldim;
    __syncthreads();
    float mu = s_mu, s2 = 0.f;
    for (int i = t; i < Ldim; i += 512) { float d = g_u[i] - mu; s2 += d*d; }
    red[t] = s2; __syncthreads();
    for (int o = 256; o > 0; o >>= 1) { if (t < o) red[t] += red[t+o]; __syncthreads(); }
    if (t == 0) s_inv = rsqrtf(red[0] / (float)Ldim + 1e-5f);
    __syncthreads();
    float inv = s_inv;
    float w1 = in_w[1], b1 = in_b[1];
    float kmin = 3.4e38f, kmax = -3.4e38f;
    for (int i = t; i < Ldim; i += 512) {
        float up = (g_u[i] - mu) * inv * ln_w[i] + ln_b[i];
        g_up[i] = up;
        float k2 = (up * w1 + b1) * LOG2E_F;
        kmin = fminf(kmin, k2); kmax = fmaxf(kmax, k2);
    }
    red[t] = kmax; __syncthreads();
    for (int o = 256; o > 0; o >>= 1) { if (t < o) red[t] = fmaxf(red[t], red[t+o]); __syncthreads(); }
    if (t == 0) g_scal[2] = red[0];
    __syncthreads();
    red[t] = kmin; __syncthreads();
    for (int o = 256; o > 0; o >>= 1) { if (t < o) red[t] = fminf(red[t], red[t+o]); __syncthreads(); }
    if (t == 0) g_scal[1] = red[0];
}

// ---------------- attention (rank-1 softmax) ----------------
__global__ __launch_bounds__(256)
void attn_kernel(const float* __restrict__ in_w, const float* __restrict__ in_b,
                 const float* __restrict__ out_w, const float* __restrict__ out_b)
{
    __shared__ float skv2[Ldim];
    __shared__ float svv[Ldim];
    int t = threadIdx.x;
    float w0 = in_w[0], b0 = in_b[0];
    float w1 = in_w[1], b1 = in_b[1];
    float w2 = in_w[2], b2 = in_b[2];
    for (int j = t; j < Ldim; j += 256) {
        float up = g_up[j];
        skv2[j] = (up * w1 + b1) * LOG2E_F;
        svv[j]  = up * w2 + b2;
    }
    __syncthreads();
    float k2min = g_scal[1], k2max = g_scal[2];
    float ow = out_w[0], ob = out_b[0];
    int warp = t >> 5, lane = t & 31;
    #pragma unroll
    for (int r = 0; r < 4; r++) {
        int i = blockIdx.x * 32 + warp * 4 + r;
        float qv = g_up[i] * w0 + b0;
        float m2 = (qv >= 0.f) ? qv * k2max : qv * k2min;
        float den = 0.f, num = 0.f;
        for (int j = lane; j < Ldim; j += 32) {
            float arg = qv * skv2[j] - m2;
            float e;
            asm("ex2.approx.f32 %0, %1;" : "=f"(e) : "f"(arg));
            den += e;
            num = fmaf(e, svv[j], num);
        }
        den = warp_sum(den); num = warp_sum(num);
        if (lane == 0) g_attn[i] = (num / den) * ow + ob;
    }
}

// ---------------- gate matvec + final fuse ----------------
__global__ __launch_bounds__(256)
void final_kernel(const float* __restrict__ W, const float* __restrict__ gb,
                  const float* __restrict__ gamma, const float* __restrict__ lmbda,
                  float* __restrict__ out)
{
    int warp = threadIdx.x >> 5, lane = threadIdx.x & 31;
    int i = blockIdx.x * 8 + warp;
    const float4* Wr = (const float4*)(W + (size_t)i * Ldim);
    const float4* U4 = (const float4*)g_u;
    float acc = 0.f;
    for (int k = lane; k < Ldim/4; k += 32) {
        float4 w4 = Wr[k]; float4 u4 = U4[k];
        acc += w4.x*u4.x + w4.y*u4.y + w4.z*u4.z + w4.w*u4.w;
    }
    acc = warp_sum(acc);
    if (lane == 0) {
        float z = acc + gb[i];
        float g = 1.f / (1.f + expf(-z));
        float s = g * g_v[i] + (1.f - g) * gamma[i] + g_attn[i] - lmbda[0];
        out[i] = fmaxf(s, 0.f);
    }
}

// ---------------- launch (single stream, round-14 order + bfn fusion) ----------------
extern "C" void kernel_launch(void* const* d_in, const int* in_sizes, int n_in,
                              void* d_out, int out_size)
{
    const float* gamma  = (const float*)d_in[0];
    const float* A_re   = (const float*)d_in[1];
    const float* A_im   = (const float*)d_in[2];
    const float* X_re   = (const float*)d_in[3];
    const float* X_im   = (const float*)d_in[4];
    const float* ln_w   = (const float*)d_in[5];
    const float* ln_b   = (const float*)d_in[6];
    const float* in_w   = (const float*)d_in[7];
    const float* in_b   = (const float*)d_in[8];
    const float* out_w  = (const float*)d_in[9];
    const float* out_b  = (const float*)d_in[10];
    const float* gate_W = (const float*)d_in[11];
    const float* gate_b = (const float*)d_in[12];
    const float* delta  = (const float*)d_in[13];
    const float* lmbda  = (const float*)d_in[14];
    float* out = (float*)d_out;

    cudaFuncSetAttribute(cgemm_mma, cudaFuncAttributeMaxDynamicSharedMemorySize, ENG_SMEM2);

    float *Rre,*Rim,*Gre,*Gim,*Xare,*Xaim,*Xbre,*Xbim,*Pre,*Pim;
    float *pre,*pim,*Atre,*Atim,*Ztre,*Ztim,*GZre,*GZim;
    cudaGetSymbolAddress((void**)&Rre,  g_Rre);   cudaGetSymbolAddress((void**)&Rim,  g_Rim);
    cudaGetSymbolAddress((void**)&Gre,  g_Gre);   cudaGetSymbolAddress((void**)&Gim,  g_Gim);
    cudaGetSymbolAddress((void**)&Xare, g_Xa_re); cudaGetSymbolAddress((void**)&Xaim, g_Xa_im);
    cudaGetSymbolAddress((void**)&Xbre, g_Xb_re); cudaGetSymbolAddress((void**)&Xbim, g_Xb_im);
    cudaGetSymbolAddress((void**)&Pre,  g_P_re);  cudaGetSymbolAddress((void**)&Pim,  g_P_im);
    cudaGetSymbolAddress((void**)&pre,  g_part_re); cudaGetSymbolAddress((void**)&pim, g_part_im);
    cudaGetSymbolAddress((void**)&Atre, g_Atre);  cudaGetSymbolAddress((void**)&Atim, g_Atim);
    cudaGetSymbolAddress((void**)&Ztre, g_Ztre);  cudaGetSymbolAddress((void**)&Ztim, g_Ztim);
    cudaGetSymbolAddress((void**)&GZre, g_GZre);  cudaGetSymbolAddress((void**)&GZim, g_GZim);

    // At = A^T (planar)
    transposeA<<<dim3(128, 8), dim3(32, 8)>>>(A_re, A_im);

    // R (Hermitian): 6 lower/diag tiles, 16-way k-split; reduce; mirror upper-right
    csyrk_big<<<dim3(6,1,16), 256>>>(pre, pim, A_re, A_im, gamma, Ldim, 256);
    reduce_RG<<<256, 256>>>(Rre, Rim, 16, 1);
    mirror_R<<<64, 256>>>();

    // G = X X^H : 2-split conj MMA (q-chain), 16-way k-split
    cgemm_mma<<<dim3(2,2,32), 256, ENG_SMEM2>>>(X_re, X_im, Tdim, X_re, X_im, Tdim,
                                                pre, pim, Mdim, 128, 1, nullptr, 65536);
    reduce_RG<<<256, 256>>>(Gre, Gim, 16, 0);

    // alpha; X1 = 2aI - a^2 R (free first Newton step)
    trace_alpha<<<1, 1024>>>();
    init_X1<<<256, 256>>>(Xare, Xaim);

    // Newton: iter0 explicit, iters1-5 with fused-newton GEMM1 (materializes Xn)
    float *Xc_re = Xare, *Xc_im = Xaim, *Xn_re = Xbre, *Xn_im = Xbim;
    cgemm_big<<<dim3(4,2,16), 256>>>(pre, pim, Rre, Rim, Mdim,
                                     Xc_re, Xc_im, Mdim, 16, 65536);
    cgemm_fsum<<<dim3(4,2,16), 256>>>(pre + (size_t)16*65536, pim + (size_t)16*65536,
                                      Xc_re, Xc_im, Mdim, pre, pim, Mdim, 16, 16, 65536);
    for (int it = 1; it < 6; ++it) {
        cgemm_bfn<<<dim3(4,2,16), 256>>>(pre, pim, Rre, Rim, Mdim,
                                         Xc_re, Xc_im, Mdim, Xn_re, Xn_im);
        cgemm_fsum<<<dim3(4,2,16), 256>>>(pre + (size_t)16*65536, pim + (size_t)16*65536,
                                          Xn_re, Xn_im, Mdim, pre, pim, Mdim, 16, 16, 65536);
        float* tmp;
        tmp = Xc_re; Xc_re = Xn_re; Xn_re = tmp;
        tmp = Xc_im; Xc_im = Xn_im; Xn_im = tmp;
    }
    reduce_newton<<<256, 256>>>(Xn_re, Xn_im, Xc_re, Xc_im, 16, 16);
    symm_conj<<<256, 256>>>(Xn_re, Xn_im, Pre, Pim);

    // Zt[l,m] = sum_k At[l,k] * Bc[k,m]   (fp32, full-K)
    cgemm_big<<<dim3(4,32,1), 256>>>(Ztre, Ztim, Atre, Atim, Mdim,
                                     Pre, Pim, Mdim, 256, 0);

    // GZt[l,m] = sum_k Zt[l,k] * G[m,k]   (2-split MMA, q-chain)
    cgemm_mma<<<dim3(2,32,2), 256, ENG_SMEM2>>>(Ztre, Ztim, Mdim, Gre, Gim, Mdim,
                                                GZre, GZim, Mdim, 256, 0, nullptr, 0);

    qduv_kernel<<<512, 256>>>(gamma, delta);
    ln_kernel<<<1, 512>>>(ln_w, ln_b, in_w, in_b);
    attn_kernel<<<128, 256>>>(in_w, in_b, out_w, out_b);
    final_kernel<<<512, 256>>>(gate_W, gate_b, gamma, lmbda, out);
}

// round 17
// speedup vs baseline: 1.3392x; 1.0336x over previous
#include <cuda_runtime.h>
#include <cuda_bf16.h>
#include <math.h>
#include <stdint.h>

#define Mdim 256
#define Ldim 4096
#define Tdim 2048
#define LOG2E_F 1.4426950408889634f

// ---------------- device scratch ----------------
__device__ float g_Rre[Mdim*Mdim], g_Rim[Mdim*Mdim];
__device__ float g_Gre[Mdim*Mdim], g_Gim[Mdim*Mdim];
__device__ float g_Xa_re[Mdim*Mdim], g_Xa_im[Mdim*Mdim];
__device__ float g_Xb_re[Mdim*Mdim], g_Xb_im[Mdim*Mdim];
__device__ float g_P_re[Mdim*Mdim],  g_P_im[Mdim*Mdim];
__device__ float g_part_re[64*Mdim*Mdim], g_part_im[64*Mdim*Mdim];
__device__ float g_Atre[Ldim*Mdim], g_Atim[Ldim*Mdim];
__device__ float g_Ztre[Ldim*Mdim], g_Ztim[Ldim*Mdim];
__device__ float g_GZre[Ldim*Mdim], g_GZim[Ldim*Mdim];
__device__ float g_v[Ldim], g_u[Ldim], g_up[Ldim], g_attn[Ldim];
__device__ float g_scal[4];   // [0]=alpha  [1]=kv2min [2]=kv2max

__device__ __forceinline__ float warp_sum(float v) {
    #pragma unroll
    for (int o = 16; o > 0; o >>= 1) v += __shfl_xor_sync(0xffffffffu, v, o);
    return v;
}

// ---------------- smem helpers ----------------
__device__ __forceinline__ uint32_t smem_u32(const void* p) {
    uint32_t a;
    asm("{ .reg .u64 t; cvta.to.shared.u64 t, %1; cvt.u32.u64 %0, t; }" : "=r"(a) : "l"(p));
    return a;
}
__device__ __forceinline__ uint32_t lds32(uint32_t a) {
    uint32_t v;
    asm volatile("ld.shared.b32 %0, [%1];" : "=r"(v) : "r"(a));
    return v;
}
__device__ __forceinline__ void sts128(uint32_t a, uint32_t x, uint32_t y,
                                       uint32_t z, uint32_t w) {
    asm volatile("st.shared.v4.b32 [%0], {%1,%2,%3,%4};"
                 :: "r"(a), "r"(x), "r"(y), "r"(z), "r"(w) : "memory");
}
__device__ __forceinline__ uint32_t cvt_tf32(float x) {
    uint32_t r;
    asm("cvt.rna.tf32.f32 %0, %1;" : "=r"(r) : "f"(x));
    return r;
}
#define MMAT32(d, a, b) \
    asm volatile("mma.sync.aligned.m16n8k8.row.col.f32.tf32.tf32.f32 " \
        "{%0,%1,%2,%3},{%4,%5,%6,%7},{%8,%9},{%0,%1,%2,%3};" \
        : "+f"((d)[0]), "+f"((d)[1]), "+f"((d)[2]), "+f"((d)[3]) \
        : "r"((a)[0]), "r"((a)[1]), "r"((a)[2]), "r"((a)[3]), "r"((b)[0]), "r"((b)[1]))

#define PITCHB 144
#define PLSZ   18432
#define ENG_SMEM2 (8*PLSZ)

// convert one 128x32 fp32 tile -> 2 tf32 split planes in smem
__device__ __forceinline__ void conv_tile2(uint32_t sa, int tbase,
                                           const float* __restrict__ src, int row0, int ld,
                                           int k0, const float* __restrict__ w, float sgn)
{
    int tid = threadIdx.x;
    uint32_t p0 = sa + tbase*PLSZ;
    uint32_t p1 = p0 + PLSZ;
    #pragma unroll
    for (int p = 0; p < 4; p++) {
        int idx = tid + p*256;
        int row = idx >> 3, c4 = idx & 7;
        float4 v = *(const float4*)(src + (size_t)(row0+row)*ld + k0 + c4*4);
        if (w) {
            float4 wv = *(const float4*)(w + k0 + c4*4);
            v.x *= wv.x; v.y *= wv.y; v.z *= wv.z; v.w *= wv.w;
        }
        v.x *= sgn; v.y *= sgn; v.z *= sgn; v.w *= sgn;
        uint32_t h0 = cvt_tf32(v.x), h1 = cvt_tf32(v.y);
        uint32_t h2 = cvt_tf32(v.z), h3 = cvt_tf32(v.w);
        uint32_t m0 = cvt_tf32(v.x - __uint_as_float(h0));
        uint32_t m1 = cvt_tf32(v.y - __uint_as_float(h1));
        uint32_t m2 = cvt_tf32(v.z - __uint_as_float(h2));
        uint32_t m3 = cvt_tf32(v.w - __uint_as_float(h3));
        uint32_t off = row*PITCHB + c4*16;
        sts128(p0 + off, h0, h1, h2, h3);
        sts128(p1 + off, m0, m1, m2, m3);
    }
}

// ============================================================================
// split-tf32 complex GEMM via mma.sync m16n8k8 (q-chain ONLY — G and GZt)
// ============================================================================
__global__ __launch_bounds__(256, 1)
void cgemm_mma(const float* __restrict__ Pre, const float* __restrict__ Pim, int ldp,
               const float* __restrict__ Qre, const float* __restrict__ Qim, int ldq,
               float* __restrict__ Cre, float* __restrict__ Cim, int ldc,
               int Kper, int conj, const float* __restrict__ w, int partElems)
{
    extern __shared__ char dsm[];
    uint32_t sa = smem_u32(dsm);
    int tid = threadIdx.x;
    int wid = tid >> 5, lane = tid & 31;
    int g = lane >> 2, t4 = lane & 3;
    int warpM = wid >> 2, warpN = wid & 3;
    int i0 = blockIdx.y * 128, j0 = blockIdx.x * 128;
    int plane = blockIdx.z & 1, ks = blockIdx.z >> 1;

    const float* A0 = (conj && plane) ? Pim : Pre;
    const float* A1 = (conj && plane) ? Pre : Pim;
    float s1 = ((conj && plane) || (!conj && !plane)) ? -1.f : 1.f;
    const float* B0 = (!conj && plane) ? Qim : Qre;
    const float* B1 = (!conj && plane) ? Qre : Qim;

    float acc[4][4][4] = {};

    int nCh = Kper >> 5;
    for (int ch = 0; ch < nCh; ch++) {
        int k0 = ks * Kper + ch * 32;
        conv_tile2(sa, 0, A0, i0, ldp, k0, w, 1.f);
        conv_tile2(sa, 2, A1, i0, ldp, k0, w, s1);
        conv_tile2(sa, 4, B0, j0, ldq, k0, (const float*)0, 1.f);
        conv_tile2(sa, 6, B1, j0, ldq, k0, (const float*)0, 1.f);
        __syncthreads();

        const int ta[6] = {0, 0, 1, 2, 2, 3};
        const int tb[6] = {4, 5, 4, 6, 7, 6};
        #pragma unroll
        for (int ps = 0; ps < 6; ps++) {
            uint32_t ab = sa + ta[ps]*PLSZ;
            uint32_t bb = sa + tb[ps]*PLSZ;
            #pragma unroll
            for (int kk = 0; kk < 4; kk++) {
                uint32_t afr[4][4], bfr[4][2];
                #pragma unroll
                for (int am = 0; am < 4; am++) {
                    uint32_t r0 = ab + (warpM*64 + am*16 + g)*PITCHB + (kk*8 + t4)*4;
                    afr[am][0] = lds32(r0);
                    afr[am][1] = lds32(r0 + 8*PITCHB);
                    afr[am][2] = lds32(r0 + 16);
                    afr[am][3] = lds32(r0 + 8*PITCHB + 16);
                }
                #pragma unroll
                for (int bn = 0; bn < 4; bn++) {
                    uint32_t r0 = bb + (warpN*32 + bn*8 + g)*PITCHB + (kk*8 + t4)*4;
                    bfr[bn][0] = lds32(r0);
                    bfr[bn][1] = lds32(r0 + 16);
                }
                #pragma unroll
                for (int am = 0; am < 4; am++)
                    #pragma unroll
                    for (int bn = 0; bn < 4; bn++)
                        MMAT32(acc[am][bn], afr[am], bfr[bn]);
            }
        }
        __syncthreads();
    }

    float* dst = plane ? Cim : Cre;
    size_t zoff = (size_t)ks * partElems;
    #pragma unroll
    for (int am = 0; am < 4; am++) {
        #pragma unroll
        for (int bn = 0; bn < 4; bn++) {
            int r = i0 + warpM*64 + am*16 + g;
            int c = j0 + warpN*32 + bn*8 + 2*t4;
            float2 v0 = make_float2(acc[am][bn][0], acc[am][bn][1]);
            float2 v1 = make_float2(acc[am][bn][2], acc[am][bn][3]);
            *(float2*)(dst + zoff + (size_t)r*ldc + c) = v0;
            *(float2*)(dst + zoff + (size_t)(r+8)*ldc + c) = v1;
        }
    }
}

// ============================================================================
// High-ILP fp32 SIMT complex GEMMs. csyrk: BM=128/TM=8. nn variants: templated.
// ============================================================================
#define BBK 16
#define BBN 64

// Hermitian csyrk: 6 lower/diagonal tiles of C = (A*diag(w)) A^H. 64-way k-split.
__global__ __launch_bounds__(256)
void csyrk_big(float* __restrict__ Pre, float* __restrict__ Pim,
               const float* __restrict__ Are, const float* __restrict__ Aim,
               const float* __restrict__ w, int lda, int kChunk)
{
    __shared__ float as_re[BBK][128+4], as_im[BBK][128+4];
    __shared__ float bs_re[BBK][BBN+4], bs_im[BBK][BBN+4];
    const int tbi[6] = {0, 0, 128, 128, 128, 128};
    const int tbj[6] = {0, 64, 0, 64, 128, 192};
    int i0 = tbi[blockIdx.x], j0 = tbj[blockIdx.x];
    int k0 = blockIdx.z * kChunk;
    int t  = threadIdx.x;
    int tx = t & 15, ty = t >> 4;
    int arow = t >> 2, ak4 = (t & 3) * 4;
    float cre[8][4] = {}, cim[8][4] = {};

    for (int kb = 0; kb < kChunk; kb += BBK) {
        int kbase = k0 + kb;
        float4 wv;
        if (w) wv = *(const float4*)(w + kbase + ak4);
        else   wv = make_float4(1.f, 1.f, 1.f, 1.f);
        #pragma unroll
        for (int r = 0; r < 2; r++) {
            int row = arow + r*64;
            float4 vr = *(const float4*)(Are + (size_t)(i0+row)*lda + kbase + ak4);
            float4 vi = *(const float4*)(Aim + (size_t)(i0+row)*lda + kbase + ak4);
            as_re[ak4+0][row] = vr.x*wv.x; as_re[ak4+1][row] = vr.y*wv.y;
            as_re[ak4+2][row] = vr.z*wv.z; as_re[ak4+3][row] = vr.w*wv.w;
            as_im[ak4+0][row] = vi.x*wv.x; as_im[ak4+1][row] = vi.y*wv.y;
            as_im[ak4+2][row] = vi.z*wv.z; as_im[ak4+3][row] = vi.w*wv.w;
        }
        {
            int col = t >> 2;
            float4 vr = *(const float4*)(Are + (size_t)(j0+col)*lda + kbase + ak4);
            float4 vi = *(const float4*)(Aim + (size_t)(j0+col)*lda + kbase + ak4);
            bs_re[ak4+0][col] = vr.x; bs_re[ak4+1][col] = vr.y;
            bs_re[ak4+2][col] = vr.z; bs_re[ak4+3][col] = vr.w;
            bs_im[ak4+0][col] = vi.x; bs_im[ak4+1][col] = vi.y;
            bs_im[ak4+2][col] = vi.z; bs_im[ak4+3][col] = vi.w;
        }
        __syncthreads();
        #pragma unroll
        for (int kk = 0; kk < BBK; kk++) {
            float ar[8], ai[8], br[4], bi[4];
            #pragma unroll
            for (int i = 0; i < 8; i++) { ar[i] = as_re[kk][ty*8+i]; ai[i] = as_im[kk][ty*8+i]; }
            #pragma unroll
            for (int j = 0; j < 4; j++) { br[j] = bs_re[kk][tx*4+j]; bi[j] = bs_im[kk][tx*4+j]; }
            #pragma unroll
            for (int i = 0; i < 8; i++)
                #pragma unroll
                for (int j = 0; j < 4; j++) {
                    cre[i][j] += ar[i]*br[j];
                    cre[i][j] += ai[i]*bi[j];
                    cim[i][j] += ai[i]*br[j];
                    cim[i][j] -= ar[i]*bi[j];
                }
        }
        __syncthreads();
    }
    size_t off = (size_t)blockIdx.z * (Mdim*Mdim);
    #pragma unroll
    for (int i = 0; i < 8; i++) {
        int gi = i0 + ty*8 + i, gj = j0 + tx*4;
        *(float4*)(Pre + off + (size_t)gi*Mdim + gj) = make_float4(cre[i][0], cre[i][1], cre[i][2], cre[i][3]);
        *(float4*)(Pim + off + (size_t)gi*Mdim + gj) = make_float4(cim[i][0], cim[i][1], cim[i][2], cim[i][3]);
    }
}

// nn variant (templated TM; BM = 16*TM): C[i,j] = sum_k A[i,k]*B[k,j]
template<int TM>
__global__ __launch_bounds__(256, 2)
void cgemm_big(float* __restrict__ Cre, float* __restrict__ Cim,
               const float* __restrict__ Are, const float* __restrict__ Aim, int lda,
               const float* __restrict__ Bre, const float* __restrict__ Bim, int ldb,
               int kChunk, int MNpart)
{
    const int BM = 16*TM;
    __shared__ float as_re[BBK][BM+4], as_im[BBK][BM+4];
    __shared__ float bs_re[BBK][BBN+4], bs_im[BBK][BBN+4];
    int i0 = blockIdx.y * BM, j0 = blockIdx.x * BBN;
    int k0 = blockIdx.z * kChunk;
    int t  = threadIdx.x;
    int tx = t & 15, ty = t >> 4;
    int arow = t >> 2, ak4 = (t & 3) * 4;
    int bk = t >> 4, bc4 = (t & 15) * 4;
    float cre[TM][4] = {}, cim[TM][4] = {};

    for (int kb = 0; kb < kChunk; kb += BBK) {
        int kbase = k0 + kb;
        #pragma unroll
        for (int r = 0; r < BM/64; r++) {
            int row = arow + r*64;
            float4 vr = *(const float4*)(Are + (size_t)(i0+row)*lda + kbase + ak4);
            float4 vi = *(const float4*)(Aim + (size_t)(i0+row)*lda + kbase + ak4);
            as_re[ak4+0][row] = vr.x; as_re[ak4+1][row] = vr.y;
            as_re[ak4+2][row] = vr.z; as_re[ak4+3][row] = vr.w;
            as_im[ak4+0][row] = vi.x; as_im[ak4+1][row] = vi.y;
            as_im[ak4+2][row] = vi.z; as_im[ak4+3][row] = vi.w;
        }
        {
            float4 vr = *(const float4*)(Bre + (size_t)(kbase+bk)*ldb + j0 + bc4);
            float4 vi = *(const float4*)(Bim + (size_t)(kbase+bk)*ldb + j0 + bc4);
            *(float4*)&bs_re[bk][bc4] = vr;
            *(float4*)&bs_im[bk][bc4] = vi;
        }
        __syncthreads();
        #pragma unroll
        for (int kk = 0; kk < BBK; kk++) {
            float ar[TM], ai[TM], br[4], bi[4];
            #pragma unroll
            for (int i = 0; i < TM; i++) { ar[i] = as_re[kk][ty*TM+i]; ai[i] = as_im[kk][ty*TM+i]; }
            #pragma unroll
            for (int j = 0; j < 4; j++) { br[j] = bs_re[kk][tx*4+j]; bi[j] = bs_im[kk][tx*4+j]; }
            #pragma unroll
            for (int i = 0; i < TM; i++)
                #pragma unroll
                for (int j = 0; j < 4; j++) {
                    cre[i][j] += ar[i]*br[j];
                    cre[i][j] -= ai[i]*bi[j];
                    cim[i][j] += ar[i]*bi[j];
                    cim[i][j] += ai[i]*br[j];
                }
        }
        __syncthreads();
    }
    size_t off = (size_t)blockIdx.z * MNpart;
    #pragma unroll
    for (int i = 0; i < TM; i++) {
        int gi = i0 + ty*TM + i, gj = j0 + tx*4;
        *(float4*)(Cre + off + (size_t)gi*ldb + gj) = make_float4(cre[i][0], cre[i][1], cre[i][2], cre[i][3]);
        *(float4*)(Cim + off + (size_t)gi*ldb + gj) = make_float4(cim[i][0], cim[i][1], cim[i][2], cim[i][3]);
    }
}

// Newton GEMM1 with fused B = 2*Xbase - sum(parts 16..31) + Xn materialization.
// A = R. grid (4, 4, 16), BM = 64.
template<int TM>
__global__ __launch_bounds__(256, 2)
void cgemm_bfn(float* __restrict__ Cre, float* __restrict__ Cim,
               const float* __restrict__ Are, const float* __restrict__ Aim, int lda,
               const float* __restrict__ Xbre, const float* __restrict__ Xbim, int ldb,
               float* __restrict__ XnRe, float* __restrict__ XnIm)
{
    const int BM = 16*TM;
    __shared__ float as_re[BBK][BM+4], as_im[BBK][BM+4];
    __shared__ float bs_re[BBK][BBN+4], bs_im[BBK][BBN+4];
    int i0 = blockIdx.y * BM, j0 = blockIdx.x * BBN;
    int kbase = blockIdx.z * BBK;
    int t  = threadIdx.x;
    int tx = t & 15, ty = t >> 4;
    int arow = t >> 2, ak4 = (t & 3) * 4;
    int bk = t >> 4, bc4 = (t & 15) * 4;
    float cre[TM][4] = {}, cim[TM][4] = {};

    #pragma unroll
    for (int r = 0; r < BM/64; r++) {
        int row = arow + r*64;
        float4 vr = *(const float4*)(Are + (size_t)(i0+row)*lda + kbase + ak4);
        float4 vi = *(const float4*)(Aim + (size_t)(i0+row)*lda + kbase + ak4);
        as_re[ak4+0][row] = vr.x; as_re[ak4+1][row] = vr.y;
        as_re[ak4+2][row] = vr.z; as_re[ak4+3][row] = vr.w;
        as_im[ak4+0][row] = vi.x; as_im[ak4+1][row] = vi.y;
        as_im[ak4+2][row] = vi.z; as_im[ak4+3][row] = vi.w;
    }
    {
        size_t eoff = (size_t)(kbase+bk)*ldb + j0 + bc4;
        float4 xr = *(const float4*)(Xbre + eoff);
        float4 xi = *(const float4*)(Xbim + eoff);
        float4 sr = make_float4(0.f,0.f,0.f,0.f), si = make_float4(0.f,0.f,0.f,0.f);
        for (int z = 16; z < 32; z++) {
            float4 pr = *(const float4*)(g_part_re + (size_t)z*65536 + eoff);
            float4 pi = *(const float4*)(g_part_im + (size_t)z*65536 + eoff);
            sr.x += pr.x; sr.y += pr.y; sr.z += pr.z; sr.w += pr.w;
            si.x += pi.x; si.y += pi.y; si.z += pi.z; si.w += pi.w;
        }
        float4 vr = make_float4(2.f*xr.x - sr.x, 2.f*xr.y - sr.y, 2.f*xr.z - sr.z, 2.f*xr.w - sr.w);
        float4 vi = make_float4(2.f*xi.x - si.x, 2.f*xi.y - si.y, 2.f*xi.z - si.z, 2.f*xi.w - si.w);
        *(float4*)&bs_re[bk][bc4] = vr;
        *(float4*)&bs_im[bk][bc4] = vi;
        if (blockIdx.y == 0) {
            *(float4*)(XnRe + eoff) = vr;
            *(float4*)(XnIm + eoff) = vi;
        }
    }
    __syncthreads();
    #pragma unroll
    for (int kk = 0; kk < BBK; kk++) {
        float ar[TM], ai[TM], br[4], bi[4];
        #pragma unroll
        for (int i = 0; i < TM; i++) { ar[i] = as_re[kk][ty*TM+i]; ai[i] = as_im[kk][ty*TM+i]; }
        #pragma unroll
        for (int j = 0; j < 4; j++) { br[j] = bs_re[kk][tx*4+j]; bi[j] = bs_im[kk][tx*4+j]; }
        #pragma unroll
        for (int i = 0; i < TM; i++)
            #pragma unroll
            for (int j = 0; j < 4; j++) {
                cre[i][j] += ar[i]*br[j];
                cre[i][j] -= ai[i]*bi[j];
                cim[i][j] += ar[i]*bi[j];
                cim[i][j] += ai[i]*br[j];
            }
    }
    __syncthreads();
    size_t off = (size_t)blockIdx.z * 65536;
    #pragma unroll
    for (int i = 0; i < TM; i++) {
        int gi = i0 + ty*TM + i, gj = j0 + tx*4;
        *(float4*)(Cre + off + (size_t)gi*ldb + gj) = make_float4(cre[i][0], cre[i][1], cre[i][2], cre[i][3]);
        *(float4*)(Cim + off + (size_t)gi*ldb + gj) = make_float4(cim[i][0], cim[i][1], cim[i][2], cim[i][3]);
    }
}

// nn variant with fused B-reduction (sum parts 0..SK-1, ascending)
template<int TM>
__global__ __launch_bounds__(256, 2)
void cgemm_fsum(float* __restrict__ Cre, float* __restrict__ Cim,
                const float* __restrict__ Are, const float* __restrict__ Aim, int lda,
                const float* __restrict__ Bpre, const float* __restrict__ Bpim, int ldb,
                int SK, int kChunk, int MNpart)
{
    const int BM = 16*TM;
    __shared__ float as_re[BBK][BM+4], as_im[BBK][BM+4];
    __shared__ float bs_re[BBK][BBN+4], bs_im[BBK][BBN+4];
    int i0 = blockIdx.y * BM, j0 = blockIdx.x * BBN;
    int k0 = blockIdx.z * kChunk;
    int t  = threadIdx.x;
    int tx = t & 15, ty = t >> 4;
    int arow = t >> 2, ak4 = (t & 3) * 4;
    int bk = t >> 4, bc4 = (t & 15) * 4;
    float cre[TM][4] = {}, cim[TM][4] = {};

    for (int kb = 0; kb < kChunk; kb += BBK) {
        int kbase = k0 + kb;
        #pragma unroll
        for (int r = 0; r < BM/64; r++) {
            int row = arow + r*64;
            float4 vr = *(const float4*)(Are + (size_t)(i0+row)*lda + kbase + ak4);
            float4 vi = *(const float4*)(Aim + (size_t)(i0+row)*lda + kbase + ak4);
            as_re[ak4+0][row] = vr.x; as_re[ak4+1][row] = vr.y;
            as_re[ak4+2][row] = vr.z; as_re[ak4+3][row] = vr.w;
            as_im[ak4+0][row] = vi.x; as_im[ak4+1][row] = vi.y;
            as_im[ak4+2][row] = vi.z; as_im[ak4+3][row] = vi.w;
        }
        {
            size_t eoff = (size_t)(kbase+bk)*ldb + j0 + bc4;
            float4 vr = make_float4(0.f,0.f,0.f,0.f), vi = make_float4(0.f,0.f,0.f,0.f);
            for (int z = 0; z < SK; z++) {
                float4 pr = *(const float4*)(Bpre + (size_t)z*65536 + eoff);
                float4 pi = *(const float4*)(Bpim + (size_t)z*65536 + eoff);
                vr.x += pr.x; vr.y += pr.y; vr.z += pr.z; vr.w += pr.w;
                vi.x += pi.x; vi.y += pi.y; vi.z += pi.z; vi.w += pi.w;
            }
            *(float4*)&bs_re[bk][bc4] = vr;
            *(float4*)&bs_im[bk][bc4] = vi;
        }
        __syncthreads();
        #pragma unroll
        for (int kk = 0; kk < BBK; kk++) {
            float ar[TM], ai[TM], br[4], bi[4];
            #pragma unroll
            for (int i = 0; i < TM; i++) { ar[i] = as_re[kk][ty*TM+i]; ai[i] = as_im[kk][ty*TM+i]; }
            #pragma unroll
            for (int j = 0; j < 4; j++) { br[j] = bs_re[kk][tx*4+j]; bi[j] = bs_im[kk][tx*4+j]; }
            #pragma unroll
            for (int i = 0; i < TM; i++)
                #pragma unroll
                for (int j = 0; j < 4; j++) {
                    cre[i][j] += ar[i]*br[j];
                    cre[i][j] -= ai[i]*bi[j];
                    cim[i][j] += ar[i]*bi[j];
                    cim[i][j] += ai[i]*br[j];
                }
        }
        __syncthreads();
    }
    size_t off = (size_t)blockIdx.z * MNpart;
    #pragma unroll
    for (int i = 0; i < TM; i++) {
        int gi = i0 + ty*TM + i, gj = j0 + tx*4;
        *(float4*)(Cre + off + (size_t)gi*ldb + gj) = make_float4(cre[i][0], cre[i][1], cre[i][2], cre[i][3]);
        *(float4*)(Cim + off + (size_t)gi*ldb + gj) = make_float4(cim[i][0], cim[i][1], cim[i][2], cim[i][3]);
    }
}

// ---------------- reduces ----------------
// R reduce with fused Hermitian mirror: for upper-right block (i<128, j>=128)
// sum the partials of the mirrored element (j,i) and conjugate — bit-identical
// to reduce-then-mirror. Ridge on diagonal.
__global__ void reduce_R_herm(float* __restrict__ Cre, float* __restrict__ Cim, int SK) {
    int e = blockIdx.x * 256 + threadIdx.x;
    int i = e >> 8, j = e & 255;
    int mirror = (i < 128 && j >= 128);
    int src = mirror ? (j*256 + i) : e;
    float sr = 0.f, si = 0.f;
    for (int z = 0; z < SK; z++) { sr += g_part_re[(size_t)z*65536 + src]; si += g_part_im[(size_t)z*65536 + src]; }
    if (mirror) si = -si;
    if (i == j) sr += 0.01f;
    Cre[e] = sr; Cim[e] = si;
}
__global__ void reduce_RG(float* __restrict__ Cre, float* __restrict__ Cim, int SK, int ridge) {
    int e = blockIdx.x * 256 + threadIdx.x;
    float sr = 0.f, si = 0.f;
    for (int z = 0; z < SK; z++) { sr += g_part_re[(size_t)z*65536 + e]; si += g_part_im[(size_t)z*65536 + e]; }
    if (ridge && (e >> 8) == (e & 255)) sr += 0.01f;
    Cre[e] = sr; Cim[e] = si;
}
// fused: Xn = 2X - sum(parts 16..31) at (i,j) and (j,i); Bc = conj(symm(Xn))
__global__ void newton_symm(const float* __restrict__ Xre, const float* __restrict__ Xim,
                            float* __restrict__ Bre, float* __restrict__ Bim)
{
    int e = blockIdx.x * 256 + threadIdx.x;
    int i = e >> 8, j = e & 255;
    int em = j*256 + i;
    float sr = 0.f, si = 0.f, mr = 0.f, mi = 0.f;
    for (int z = 16; z < 32; z++) {
        sr += g_part_re[(size_t)z*65536 + e];  si += g_part_im[(size_t)z*65536 + e];
        mr += g_part_re[(size_t)z*65536 + em]; mi += g_part_im[(size_t)z*65536 + em];
    }
    float xnij_re = 2.f*Xre[e]  - sr, xnij_im = 2.f*Xim[e]  - si;
    float xnji_re = 2.f*Xre[em] - mr, xnji_im = 2.f*Xim[em] - mi;
    Bre[e] = 0.5f * (xnij_re + xnji_re);
    Bim[e] = 0.5f * (xnji_im - xnij_im);
}

// ---------------- alpha ; X1 = 2aI - a^2 R ----------------
__global__ void trace_alpha() {
    __shared__ float red[1024];
    __shared__ float s_fro;
    int t = threadIdx.x;
    float fro = 0.f;
    for (int e = t; e < 65536; e += 1024) {
        float a = g_Rre[e], b = g_Rim[e];
        fro += a*a + b*b;
    }
    red[t] = fro; __syncthreads();
    for (int o = 512; o > 0; o >>= 1) { if (t < o) red[t] += red[t+o]; __syncthreads(); }
    if (t == 0) s_fro = red[0];
    __syncthreads();
    float tr = 0.f;
    for (int i = t; i < 256; i += 1024) tr += g_Rre[i*257];
    red[t] = tr; __syncthreads();
    for (int o = 512; o > 0; o >>= 1) { if (t < o) red[t] += red[t+o]; __syncthreads(); }
    if (t == 0) g_scal[0] = red[0] / s_fro;
}
__global__ void init_X1(float* __restrict__ Xre, float* __restrict__ Xim) {
    int e = blockIdx.x * 256 + threadIdx.x;
    int i = e >> 8, j = e & 255;
    float a = g_scal[0];
    float a2 = a * a;
    Xre[e] = -a2 * g_Rre[e] + ((i == j) ? 2.f*a : 0.f);
    Xim[e] = -a2 * g_Rim[e];
}

// ---------------- transpose A -> At [L][M] ----------------
__global__ void transposeA(const float* __restrict__ Are, const float* __restrict__ Aim) {
    __shared__ float t0[32][33], t1[32][33];
    int lb = blockIdx.x * 32, mb = blockIdx.y * 32;
    int x = threadIdx.x, y = threadIdx.y;
    for (int yy = y; yy < 32; yy += 8) {
        t0[yy][x] = Are[(size_t)(mb+yy)*Ldim + lb + x];
        t1[yy][x] = Aim[(size_t)(mb+yy)*Ldim + lb + x];
    }
    __syncthreads();
    for (int yy = y; yy < 32; yy += 8) {
        g_Atre[(size_t)(lb+yy)*Mdim + mb + x] = t0[x][yy];
        g_Atim[(size_t)(lb+yy)*Mdim + mb + x] = t1[x][yy];
    }
}

// ---------------- q, d, v, u ----------------
__global__ __launch_bounds__(256)
void qduv_kernel(const float* __restrict__ gamma, const float* __restrict__ delta) {
    int wid = threadIdx.x >> 5, lane = threadIdx.x & 31;
    int l = blockIdx.x * 8 + wid;
    const float4* zr  = (const float4*)(g_Ztre + (size_t)l*Mdim);
    const float4* zi  = (const float4*)(g_Ztim + (size_t)l*Mdim);
    const float4* gr  = (const float4*)(g_GZre + (size_t)l*Mdim);
    const float4* gi  = (const float4*)(g_GZim + (size_t)l*Mdim);
    const float4* ar  = (const float4*)(g_Atre + (size_t)l*Mdim);
    const float4* ai  = (const float4*)(g_Atim + (size_t)l*Mdim);
    float q = 0.f, d = 0.f;
    #pragma unroll
    for (int it = 0; it < 2; it++) {
        int k = lane + it*32;
        float4 a = zr[k], b = zi[k], c = gr[k], e = gi[k], f = ar[k], g2 = ai[k];
        q += a.x*c.x + a.y*c.y + a.z*c.z + a.w*c.w
           + b.x*e.x + b.y*e.y + b.z*e.z + b.w*e.w;
        d += a.x*f.x + a.y*f.y + a.z*f.z + a.w*f.w
           - (b.x*g2.x + b.y*g2.y + b.z*g2.z + b.w*g2.w);
    }
    q = warp_sum(q); d = warp_sum(d);
    if (lane == 0) {
        float v = q / (d + 1e-12f);
        float dl = 1.f / (1.f + expf(-delta[0]));
        float p = gamma[l];
        g_v[l] = v;
        g_u[l] = p + dl * (v - p);
    }
}

// ---------------- LayerNorm + kv stats ----------------
__global__ void ln_kernel(const float* __restrict__ ln_w, const float* __restrict__ ln_b,
                          const float* __restrict__ in_w, const float* __restrict__ in_b)
{
    __shared__ float red[512];
    __shared__ float s_mu, s_inv;
    int t = threadIdx.x;
    float s = 0.f;
    for (int i = t; i < Ldim; i += 512) s += g_u[i];
    red[t] = s; __syncthreads();
    for (int o = 256; o > 0; o >>= 1) { if (t < o) red[t] += red[t+o]; __syncthreads(); }
    if (t == 0) s_mu = red[0] / (float)Ldim;
    __syncthreads();
    float mu = s_mu, s2 = 0.f;
    for (int i = t; i < Ldim; i += 512) { float d = g_u[i] - mu; s2 += d*d; }
    red[t] = s2; __syncthreads();
    for (int o = 256; o > 0; o >>= 1) { if (t < o) red[t] += red[t+o]; __syncthreads(); }
    if (t == 0) s_inv = rsqrtf(red[0] / (float)Ldim + 1e-5f);
    __syncthreads();
    float inv = s_inv;
    float w1 = in_w[1], b1 = in_b[1];
    float kmin = 3.4e38f, kmax = -3.4e38f;
    for (int i = t; i < Ldim; i += 512) {
        float up = (g_u[i] - mu) * inv * ln_w[i] + ln_b[i];
        g_up[i] = up;
        float k2 = (up * w1 + b1) * LOG2E_F;
        kmin = fminf(kmin, k2); kmax = fmaxf(kmax, k2);
    }
    red[t] = kmax; __syncthreads();
    for (int o = 256; o > 0; o >>= 1) { if (t < o) red[t] = fmaxf(red[t], red[t+o]); __syncthreads(); }
    if (t == 0) g_scal[2] = red[0];
    __syncthreads();
    red[t] = kmin; __syncthreads();
    for (int o = 256; o > 0; o >>= 1) { if (t < o) red[t] = fminf(red[t], red[t+o]); __syncthreads(); }
    if (t == 0) g_scal[1] = red[0];
}

// ---------------- attention (rank-1 softmax) ----------------
__global__ __launch_bounds__(256)
void attn_kernel(const float* __restrict__ in_w, const float* __restrict__ in_b,
                 const float* __restrict__ out_w, const float* __restrict__ out_b)
{
    __shared__ float skv2[Ldim];
    __shared__ float svv[Ldim];
    int t = threadIdx.x;
    float w0 = in_w[0], b0 = in_b[0];
    float w1 = in_w[1], b1 = in_b[1];
    float w2 = in_w[2], b2 = in_b[2];
    for (int j = t; j < Ldim; j += 256) {
        float up = g_up[j];
        skv2[j] = (up * w1 + b1) * LOG2E_F;
        svv[j]  = up * w2 + b2;
    }
    __syncthreads();
    float k2min = g_scal[1], k2max = g_scal[2];
    float ow = out_w[0], ob = out_b[0];
    int warp = t >> 5, lane = t & 31;
    #pragma unroll
    for (int r = 0; r < 4; r++) {
        int i = blockIdx.x * 32 + warp * 4 + r;
        float qv = g_up[i] * w0 + b0;
        float m2 = (qv >= 0.f) ? qv * k2max : qv * k2min;
        float den = 0.f, num = 0.f;
        for (int j = lane; j < Ldim; j += 32) {
            float arg = qv * skv2[j] - m2;
            float e;
            asm("ex2.approx.f32 %0, %1;" : "=f"(e) : "f"(arg));
            den += e;
            num = fmaf(e, svv[j], num);
        }
        den = warp_sum(den); num = warp_sum(num);
        if (lane == 0) g_attn[i] = (num / den) * ow + ob;
    }
}

// ---------------- gate matvec + final fuse ----------------
__global__ __launch_bounds__(256)
void final_kernel(const float* __restrict__ W, const float* __restrict__ gb,
                  const float* __restrict__ gamma, const float* __restrict__ lmbda,
                  float* __restrict__ out)
{
    int warp = threadIdx.x >> 5, lane = threadIdx.x & 31;
    int i = blockIdx.x * 8 + warp;
    const float4* Wr = (const float4*)(W + (size_t)i * Ldim);
    const float4* U4 = (const float4*)g_u;
    float acc = 0.f;
    for (int k = lane; k < Ldim/4; k += 32) {
        float4 w4 = Wr[k]; float4 u4 = U4[k];
        acc += w4.x*u4.x + w4.y*u4.y + w4.z*u4.z + w4.w*u4.w;
    }
    acc = warp_sum(acc);
    if (lane == 0) {
        float z = acc + gb[i];
        float g = 1.f / (1.f + expf(-z));
        float s = g * g_v[i] + (1.f - g) * gamma[i] + g_attn[i] - lmbda[0];
        out[i] = fmaxf(s, 0.f);
    }
}

// ---------------- launch ----------------
extern "C" void kernel_launch(void* const* d_in, const int* in_sizes, int n_in,
                              void* d_out, int out_size)
{
    const float* gamma  = (const float*)d_in[0];
    const float* A_re   = (const float*)d_in[1];
    const float* A_im   = (const float*)d_in[2];
    const float* X_re   = (const float*)d_in[3];
    const float* X_im   = (const float*)d_in[4];
    const float* ln_w   = (const float*)d_in[5];
    const float* ln_b   = (const float*)d_in[6];
    const float* in_w   = (const float*)d_in[7];
    const float* in_b   = (const float*)d_in[8];
    const float* out_w  = (const float*)d_in[9];
    const float* out_b  = (const float*)d_in[10];
    const float* gate_W = (const float*)d_in[11];
    const float* gate_b = (const float*)d_in[12];
    const float* delta  = (const float*)d_in[13];
    const float* lmbda  = (const float*)d_in[14];
    float* out = (float*)d_out;

    cudaFuncSetAttribute(cgemm_mma, cudaFuncAttributeMaxDynamicSharedMemorySize, ENG_SMEM2);

    float *Rre,*Rim,*Gre,*Gim,*Xare,*Xaim,*Xbre,*Xbim,*Pre,*Pim;
    float *pre,*pim,*Atre,*Atim,*Ztre,*Ztim,*GZre,*GZim;
    cudaGetSymbolAddress((void**)&Rre,  g_Rre);   cudaGetSymbolAddress((void**)&Rim,  g_Rim);
    cudaGetSymbolAddress((void**)&Gre,  g_Gre);   cudaGetSymbolAddress((void**)&Gim,  g_Gim);
    cudaGetSymbolAddress((void**)&Xare, g_Xa_re); cudaGetSymbolAddress((void**)&Xaim, g_Xa_im);
    cudaGetSymbolAddress((void**)&Xbre, g_Xb_re); cudaGetSymbolAddress((void**)&Xbim, g_Xb_im);
    cudaGetSymbolAddress((void**)&Pre,  g_P_re);  cudaGetSymbolAddress((void**)&Pim,  g_P_im);
    cudaGetSymbolAddress((void**)&pre,  g_part_re); cudaGetSymbolAddress((void**)&pim, g_part_im);
    cudaGetSymbolAddress((void**)&Atre, g_Atre);  cudaGetSymbolAddress((void**)&Atim, g_Atim);
    cudaGetSymbolAddress((void**)&Ztre, g_Ztre);  cudaGetSymbolAddress((void**)&Ztim, g_Ztim);
    cudaGetSymbolAddress((void**)&GZre, g_GZre);  cudaGetSymbolAddress((void**)&GZim, g_GZim);

    // At = A^T (planar)
    transposeA<<<dim3(128, 8), dim3(32, 8)>>>(A_re, A_im);

    // R (Hermitian): 6 tiles x 64-way k-split = 384 CTAs (full chip); fused
    // reduce+mirror+ridge
    csyrk_big<<<dim3(6,1,64), 256>>>(pre, pim, A_re, A_im, gamma, Ldim, 64);
    reduce_R_herm<<<256, 256>>>(Rre, Rim, 64);

    // G = X X^H : 2-split conj MMA (q-chain), 16-way k-split (slots 0..15)
    cgemm_mma<<<dim3(2,2,32), 256, ENG_SMEM2>>>(X_re, X_im, Tdim, X_re, X_im, Tdim,
                                                pre, pim, Mdim, 128, 1, nullptr, 65536);
    reduce_RG<<<256, 256>>>(Gre, Gim, 16, 0);

    // alpha; X1 = 2aI - a^2 R (free first Newton step)
    trace_alpha<<<1, 1024>>>();
    init_X1<<<256, 256>>>(Xare, Xaim);

    // Newton (BM=64 grids, 256 CTAs each, 2 CTA/SM):
    // iter0 explicit; iters1-5 fused-newton GEMM1 (materializes Xn)
    float *Xc_re = Xare, *Xc_im = Xaim, *Xn_re = Xbre, *Xn_im = Xbim;
    cgemm_big<4><<<dim3(4,4,16), 256>>>(pre, pim, Rre, Rim, Mdim,
                                        Xc_re, Xc_im, Mdim, 16, 65536);
    cgemm_fsum<4><<<dim3(4,4,16), 256>>>(pre + (size_t)16*65536, pim + (size_t)16*65536,
                                         Xc_re, Xc_im, Mdim, pre, pim, Mdim, 16, 16, 65536);
    for (int it = 1; it < 6; ++it) {
        cgemm_bfn<4><<<dim3(4,4,16), 256>>>(pre, pim, Rre, Rim, Mdim,
                                            Xc_re, Xc_im, Mdim, Xn_re, Xn_im);
        cgemm_fsum<4><<<dim3(4,4,16), 256>>>(pre + (size_t)16*65536, pim + (size_t)16*65536,
                                             Xn_re, Xn_im, Mdim, pre, pim, Mdim, 16, 16, 65536);
        float* tmp;
        tmp = Xc_re; Xc_re = Xn_re; Xn_re = tmp;
        tmp = Xc_im; Xc_im = Xn_im; Xn_im = tmp;
    }
    // fused final reduce + Hermitian-conj projection -> Bc (in g_P)
    newton_symm<<<256, 256>>>(Xc_re, Xc_im, Pre, Pim);

    // Zt[l,m] = sum_k At[l,k] * Bc[k,m]   (fp32, full-K, BM=64: 256 CTAs)
    cgemm_big<4><<<dim3(4,64,1), 256>>>(Ztre, Ztim, Atre, Atim, Mdim,
                                        Pre, Pim, Mdim, 256, 0);

    // GZt[l,m] = sum_k Zt[l,k] * G[m,k]   (2-split MMA, q-chain)
    cgemm_mma<<<dim3(2,32,2), 256, ENG_SMEM2>>>(Ztre, Ztim, Mdim, Gre, Gim, Mdim,
                                                GZre, GZim, Mdim, 256, 0, nullptr, 0);

    qduv_kernel<<<512, 256>>>(gamma, delta);
    ln_kernel<<<1, 512>>>(ln_w, ln_b, in_w, in_b);
    attn_kernel<<<128, 256>>>(in_w, in_b, out_w, out_b);
    final_kernel<<<512, 256>>>(gate_W, gate_b, gamma, lmbda, out);
}